// round 5
// baseline (speedup 1.0000x reference)
#include <cuda_runtime.h>
#include <cuda_bf16.h>
#include <math.h>

// Problem constants
#define BB 128
#define TT 64
#define DD 1024
#define HH 16
#define HDD 64
#define BT (BB*TT)        // 8192
#define PAD 68

// Scratch (device globals: allocation-free rule)
__device__ float g_q[BT*DD];
__device__ float g_k[BT*DD];
__device__ float g_v[BT*DD];
__device__ float g_att[BT*DD];

__device__ __forceinline__ float to_tf32(float x) {
    float r;
    asm("cvt.rna.tf32.f32 %0, %1;" : "=f"(r) : "f"(x));
    return r;
}
__device__ __forceinline__ unsigned tf32_bits(float x) {
    return __float_as_uint(to_tf32(x));
}

__device__ __forceinline__ void mma_tf32(float c[4], const unsigned a[4], const unsigned b[2]) {
    asm volatile(
        "mma.sync.aligned.m16n8k8.row.col.f32.tf32.tf32.f32 "
        "{%0,%1,%2,%3}, {%4,%5,%6,%7}, {%8,%9}, {%0,%1,%2,%3};"
        : "+f"(c[0]), "+f"(c[1]), "+f"(c[2]), "+f"(c[3])
        : "r"(a[0]), "r"(a[1]), "r"(a[2]), "r"(a[3]),
          "r"(b[0]), "r"(b[1]));
}

__device__ __forceinline__ void cp_async16(void* smem, const void* gmem) {
    unsigned s = (unsigned)__cvta_generic_to_shared(smem);
    asm volatile("cp.async.ca.shared.global [%0], [%1], 16;\n" :: "r"(s), "l"(gmem));
}
#define CP_COMMIT() asm volatile("cp.async.commit_group;\n" ::: "memory")
#define CP_WAIT0()  asm volatile("cp.async.wait_group 0;\n" ::: "memory")

// ---------------------------------------------------------------------------
// TF32 tensor-core GEMM, cp.async double-buffered.
// C[M,N] = A[M,K] @ W[K,N], row-major fp32. BM=BN=128, BK=32, 256 thr.
// If nW > 1: blockIdx.z selects among Ws[] / Cs[] (fused QKV projections).
// ---------------------------------------------------------------------------
#define SA_ST 4608   // 128*36
#define SB_ST 4352   // 32*136
#define GEMM_SMEM ((2*SA_ST + 2*SB_ST) * 4)

__global__ __launch_bounds__(256) void tf32_gemm_kernel(
    const float* __restrict__ A,
    const float* __restrict__ W0, const float* __restrict__ W1,
    const float* __restrict__ W2,
    float* __restrict__ C0, float* __restrict__ C1, float* __restrict__ C2,
    int M, int N, int K)
{
    extern __shared__ float dsm[];
    float* sAb = dsm;                 // [2][128][36]
    float* sBb = dsm + 2 * SA_ST;     // [2][32][136]

    const float* W = (blockIdx.z == 0) ? W0 : (blockIdx.z == 1) ? W1 : W2;
    float*       C = (blockIdx.z == 0) ? C0 : (blockIdx.z == 1) ? C1 : C2;

    const int tid  = threadIdx.x;
    const int lane = tid & 31;
    const int wid  = tid >> 5;
    const int wm   = (wid & 3) * 32;
    const int wn   = (wid >> 2) * 64;
    const int g    = lane >> 2;
    const int t    = lane & 3;

    const int m0 = blockIdx.y * 128;
    const int n0 = blockIdx.x * 128;

    float acc[2][8][4];
#pragma unroll
    for (int mt = 0; mt < 2; mt++)
#pragma unroll
        for (int nt = 0; nt < 8; nt++)
#pragma unroll
            for (int i = 0; i < 4; i++) acc[mt][nt][i] = 0.f;

    auto load_stage = [&](int st, int k0) {
        float* sA = sAb + st * SA_ST;
        float* sB = sBb + st * SB_ST;
#pragma unroll
        for (int r = 0; r < 4; r++) {
            int f   = tid + r * 256;
            int row = f >> 3;
            int c4  = (f & 7) * 4;
            cp_async16(&sA[row * 36 + c4],
                       &A[(size_t)(m0 + row) * K + k0 + c4]);
        }
#pragma unroll
        for (int r = 0; r < 4; r++) {
            int f   = tid + r * 256;
            int row = f >> 5;
            int c4  = (f & 31) * 4;
            cp_async16(&sB[row * 136 + c4],
                       &W[(size_t)(k0 + row) * N + n0 + c4]);
        }
    };

    load_stage(0, 0);
    CP_COMMIT();
    CP_WAIT0();
    __syncthreads();

    int st = 0;
    for (int k0 = 0; k0 < K; k0 += 32) {
        const int nxt = k0 + 32;
        if (nxt < K) {
            load_stage(st ^ 1, nxt);
            CP_COMMIT();
        }

        const float* sA = sAb + st * SA_ST;
        const float* sB = sBb + st * SB_ST;
#pragma unroll
        for (int ks = 0; ks < 4; ks++) {
            const int kb = ks * 8;
            unsigned af[2][4];
#pragma unroll
            for (int mt = 0; mt < 2; mt++) {
                const int row = wm + mt * 16;
                af[mt][0] = tf32_bits(sA[(row + g    ) * 36 + kb + t    ]);
                af[mt][1] = tf32_bits(sA[(row + g + 8) * 36 + kb + t    ]);
                af[mt][2] = tf32_bits(sA[(row + g    ) * 36 + kb + t + 4]);
                af[mt][3] = tf32_bits(sA[(row + g + 8) * 36 + kb + t + 4]);
            }
            unsigned bf[8][2];
#pragma unroll
            for (int nt = 0; nt < 8; nt++) {
                const int col = wn + nt * 8 + g;
                bf[nt][0] = tf32_bits(sB[(kb + t    ) * 136 + col]);
                bf[nt][1] = tf32_bits(sB[(kb + t + 4) * 136 + col]);
            }
#pragma unroll
            for (int mt = 0; mt < 2; mt++)
#pragma unroll
                for (int nt = 0; nt < 8; nt++)
                    mma_tf32(acc[mt][nt], af[mt], bf[nt]);
        }

        if (nxt < K) CP_WAIT0();
        __syncthreads();
        st ^= 1;
    }

#pragma unroll
    for (int mt = 0; mt < 2; mt++) {
#pragma unroll
        for (int nt = 0; nt < 8; nt++) {
            const size_t row = (size_t)(m0 + wm + mt * 16 + g);
            const int    col = n0 + wn + nt * 8 + 2 * t;
            float2 lo = make_float2(acc[mt][nt][0], acc[mt][nt][1]);
            float2 hi = make_float2(acc[mt][nt][2], acc[mt][nt][3]);
            *reinterpret_cast<float2*>(&C[row * N + col])       = lo;
            *reinterpret_cast<float2*>(&C[(row + 8) * N + col]) = hi;
        }
    }
}

// ---------------------------------------------------------------------------
// Fused smolgen attention v4: one block per (b, q). 256 threads, 4 blocks/SM.
// No K/V smem staging (direct L2 reads); 2 barriers per head;
// per-warp redundant softmax; probs distributed via shfl.
// ---------------------------------------------------------------------------
__global__ __launch_bounds__(256, 4) void attn_kernel(
    const float* __restrict__ Q, const float* __restrict__ Kt,
    const float* __restrict__ V,
    const float* __restrict__ AQ, const float* __restrict__ AK,
    const float* __restrict__ AV, float* __restrict__ Out)
{
    extern __shared__ float smem[];
    float* sQ  = smem;                  // 1024
    float* sAk = sQ  + HH * HDD;        // 64*PAD
    float* sAv = sAk + TT * PAD;        // 64*PAD
    float* sLog = sAv + TT * PAD;       // 64
    float* sRed = sLog + TT;            // 256

    const int tid  = threadIdx.x;
    const int lane = tid & 31;
    const size_t row = (size_t)blockIdx.x;
    const int b = blockIdx.x >> 6;

    const int lk  = tid >> 2;           // 0..63  (logits k index)
    const int lp  = tid & 3;            // 0..3   (logits d-phase)
    const int od  = tid & 63;           // output d index
    const int okp = tid >> 6;           // output k-quarter (uniform per warp)

    // Prologue
    {
        const float4* src = reinterpret_cast<const float4*>(Q + row * DD);
        reinterpret_cast<float4*>(sQ)[tid] = src[tid];
    }
    {
        const float4* k4 = reinterpret_cast<const float4*>(AK + row * TT * HDD);
        const float4* v4 = reinterpret_cast<const float4*>(AV + row * TT * HDD);
#pragma unroll
        for (int r = 0; r < 4; r++) {
            int f  = tid + r * 256;
            int kk = f >> 4;
            int c4 = (f & 15) * 4;
            *reinterpret_cast<float4*>(&sAk[kk * PAD + c4]) = k4[f];
            *reinterpret_cast<float4*>(&sAv[kk * PAD + c4]) = v4[f];
        }
    }
    float aq_r[16];
    {
        const float* aqp = AQ + row * TT * HDD + lk * HDD + lp;
#pragma unroll
        for (int i = 0; i < 16; i++) aq_r[i] = aqp[4 * i];
    }
    __syncthreads();

    // base pointers for direct K/V reads (L2 resident across the 64 q-blocks of b)
    const float* kbase = Kt + (size_t)b * TT * DD + lk * DD + lp;
    const float* vbase = V  + (size_t)b * TT * DD + (size_t)okp * 16 * DD + od;

    for (int h = 0; h < HH; h++) {
        const int hoff = h * HDD;

        // ---- logits: direct K loads, a_q regs, a_k smem (conflict-free) ----
        {
            const float* qh = sQ + hoff;
            const float* kp = kbase + hoff;
            float c = 0.f, bq = 0.f, bk = 0.f;
#pragma unroll
            for (int i = 0; i < 16; i++) {
                int d = lp + 4 * i;
                float kv = kp[4 * i];           // K[b, lk, h, d]
                float qv = qh[d];
                c  += qv * kv;
                bq += aq_r[i] * kv;
                bk += qv * sAk[lk * PAD + d];
            }
            float l = c * 0.125f + bq + bk;
            l += __shfl_xor_sync(0xffffffffu, l, 1);
            l += __shfl_xor_sync(0xffffffffu, l, 2);
            if (lp == 0) sLog[lk] = l;
        }
        __syncthreads();                        // barrier A: sLog ready

        // ---- per-warp redundant softmax ----
        float p0, p1;
        {
            float a  = sLog[lane];
            float b2 = sLog[lane + 32];
            float m = fmaxf(a, b2);
#pragma unroll
            for (int o = 16; o; o >>= 1)
                m = fmaxf(m, __shfl_xor_sync(0xffffffffu, m, o));
            float ea = __expf(a - m), eb = __expf(b2 - m);
            float s = ea + eb;
#pragma unroll
            for (int o = 16; o; o >>= 1)
                s += __shfl_xor_sync(0xffffffffu, s, o);
            float inv = 1.0f / s;
            p0 = ea * inv;                      // p[lane]
            p1 = eb * inv;                      // p[lane+32]
        }

        // ---- output: direct V loads (coalesced), probs via shfl broadcast ----
        {
            const float* vp = vbase + hoff;
            float acc = 0.f;
#pragma unroll
            for (int i = 0; i < 16; i++) {
                int k = okp * 16 + i;
                float pk = __shfl_sync(0xffffffffu, (okp < 2) ? p0 : p1, k & 31);
                acc += pk * (vp[(size_t)i * DD] + sAv[k * PAD + od]);
            }
            sRed[tid] = acc;
        }
        __syncthreads();                        // barrier B: sRed ready
        if (tid < 64) {
            float o = sRed[tid] + sRed[tid + 64] + sRed[tid + 128] + sRed[tid + 192];
            Out[row * DD + hoff + tid] = o;
        }
        // sLog/sRed reuse for head h+1 is ordered by barrier B (writes occur
        // only after the next barrier A / after this barrier respectively).
    }
}

// ---------------------------------------------------------------------------
extern "C" void kernel_launch(void* const* d_in, const int* in_sizes, int n_in,
                              void* d_out, int out_size)
{
    const float* x  = (const float*)d_in[0];
    const float* aq = (const float*)d_in[1];
    const float* ak = (const float*)d_in[2];
    const float* av = (const float*)d_in[3];
    const float* Wq = (const float*)d_in[4];
    const float* Wk = (const float*)d_in[5];
    const float* Wv = (const float*)d_in[6];
    const float* Wo = (const float*)d_in[7];
    float* out = (float*)d_out;

    float *pq, *pk, *pv, *patt;
    cudaGetSymbolAddress((void**)&pq,   g_q);
    cudaGetSymbolAddress((void**)&pk,   g_k);
    cudaGetSymbolAddress((void**)&pv,   g_v);
    cudaGetSymbolAddress((void**)&patt, g_att);

    cudaFuncSetAttribute((const void*)tf32_gemm_kernel,
                         cudaFuncAttributeMaxDynamicSharedMemorySize, GEMM_SMEM);

    // fused QKV projections: grid.z picks W / C
    dim3 qkv_grid(DD / 128, BT / 128, 3);
    tf32_gemm_kernel<<<qkv_grid, 256, GEMM_SMEM>>>(
        x, Wq, Wk, Wv, pq, pk, pv, BT, DD, DD);

    const int smem_bytes = (HH*HDD + 2 * TT * PAD + TT + 256) * (int)sizeof(float);
    cudaFuncSetAttribute((const void*)attn_kernel,
                         cudaFuncAttributeMaxDynamicSharedMemorySize, smem_bytes);
    attn_kernel<<<BT, 256, smem_bytes>>>(pq, pk, pv, aq, ak, av, patt);

    dim3 o_grid(DD / 128, BT / 128, 1);
    tf32_gemm_kernel<<<o_grid, 256, GEMM_SMEM>>>(
        patt, Wo, Wo, Wo, out, out, out, BT, DD, DD);
}

// round 6
// speedup vs baseline: 1.0911x; 1.0911x over previous
#include <cuda_runtime.h>
#include <cuda_bf16.h>
#include <math.h>

// Problem constants
#define BB 128
#define TT 64
#define DD 1024
#define HH 16
#define HDD 64
#define BT (BB*TT)        // 8192

// Scratch (device globals: allocation-free rule)
__device__ float g_q[BT*DD];
__device__ float g_k[BT*DD];
__device__ float g_v[BT*DD];
__device__ float g_att[BT*DD];
__device__ float g_xt[BT*DD];       // tf32-rounded x
__device__ float g_wt[4*DD*DD];     // tf32-rounded Wq,Wk,Wv,Wo

__device__ __forceinline__ float to_tf32(float x) {
    float r;
    asm("cvt.rna.tf32.f32 %0, %1;" : "=f"(r) : "f"(x));
    return r;
}

__device__ __forceinline__ void mma_tf32(float c[4], const unsigned a[4], const unsigned b[2]) {
    asm volatile(
        "mma.sync.aligned.m16n8k8.row.col.f32.tf32.tf32.f32 "
        "{%0,%1,%2,%3}, {%4,%5,%6,%7}, {%8,%9}, {%0,%1,%2,%3};"
        : "+f"(c[0]), "+f"(c[1]), "+f"(c[2]), "+f"(c[3])
        : "r"(a[0]), "r"(a[1]), "r"(a[2]), "r"(a[3]),
          "r"(b[0]), "r"(b[1]));
}

__device__ __forceinline__ void cp_async16(void* smem, const void* gmem) {
    unsigned s = (unsigned)__cvta_generic_to_shared(smem);
    asm volatile("cp.async.ca.shared.global [%0], [%1], 16;\n" :: "r"(s), "l"(gmem));
}
#define CP_COMMIT() asm volatile("cp.async.commit_group;\n" ::: "memory")
#define CP_WAIT0()  asm volatile("cp.async.wait_group 0;\n" ::: "memory")

// ---------------------------------------------------------------------------
// tf32 pre-round pass: dst[i] = tf32(src[i]) (float4 grid-stride)
// ---------------------------------------------------------------------------
__global__ __launch_bounds__(256) void cvt_tf32_kernel(
    const float* __restrict__ src, float* __restrict__ dst, int n4)
{
    int i = blockIdx.x * blockDim.x + threadIdx.x;
    int stride = gridDim.x * blockDim.x;
    const float4* s4 = reinterpret_cast<const float4*>(src);
    float4* d4 = reinterpret_cast<float4*>(dst);
    for (; i < n4; i += stride) {
        float4 v = s4[i];
        v.x = to_tf32(v.x); v.y = to_tf32(v.y);
        v.z = to_tf32(v.z); v.w = to_tf32(v.w);
        d4[i] = v;
    }
}

// ---------------------------------------------------------------------------
// TF32 tensor-core GEMM, cp.async double-buffered, NO in-loop cvt
// (inputs pre-rounded). C[M,N] = A[M,K] @ W[K,N]. BM=BN=128, BK=32, 256 thr.
// blockIdx.z selects among W0..2 / C0..2.
// ---------------------------------------------------------------------------
#define SA_ST 4608   // 128*36
#define SB_ST 4352   // 32*136
#define GEMM_SMEM ((2*SA_ST + 2*SB_ST) * 4)

__global__ __launch_bounds__(256) void tf32_gemm_kernel(
    const float* __restrict__ A,
    const float* __restrict__ W0, const float* __restrict__ W1,
    const float* __restrict__ W2,
    float* __restrict__ C0, float* __restrict__ C1, float* __restrict__ C2,
    int M, int N, int K)
{
    extern __shared__ float dsm[];
    float* sAb = dsm;                 // [2][128][36]
    float* sBb = dsm + 2 * SA_ST;     // [2][32][136]

    const float* W = (blockIdx.z == 0) ? W0 : (blockIdx.z == 1) ? W1 : W2;
    float*       C = (blockIdx.z == 0) ? C0 : (blockIdx.z == 1) ? C1 : C2;

    const int tid  = threadIdx.x;
    const int lane = tid & 31;
    const int wid  = tid >> 5;
    const int wm   = (wid & 3) * 32;
    const int wn   = (wid >> 2) * 64;
    const int g    = lane >> 2;
    const int t    = lane & 3;

    const int m0 = blockIdx.y * 128;
    const int n0 = blockIdx.x * 128;

    float acc[2][8][4];
#pragma unroll
    for (int mt = 0; mt < 2; mt++)
#pragma unroll
        for (int nt = 0; nt < 8; nt++)
#pragma unroll
            for (int i = 0; i < 4; i++) acc[mt][nt][i] = 0.f;

    auto load_stage = [&](int st, int k0) {
        float* sA = sAb + st * SA_ST;
        float* sB = sBb + st * SB_ST;
#pragma unroll
        for (int r = 0; r < 4; r++) {
            int f   = tid + r * 256;
            int row = f >> 3;
            int c4  = (f & 7) * 4;
            cp_async16(&sA[row * 36 + c4],
                       &A[(size_t)(m0 + row) * K + k0 + c4]);
        }
#pragma unroll
        for (int r = 0; r < 4; r++) {
            int f   = tid + r * 256;
            int row = f >> 5;
            int c4  = (f & 31) * 4;
            cp_async16(&sB[row * 136 + c4],
                       &W[(size_t)(k0 + row) * N + n0 + c4]);
        }
    };

    load_stage(0, 0);
    CP_COMMIT();
    CP_WAIT0();
    __syncthreads();

    int st = 0;
    for (int k0 = 0; k0 < K; k0 += 32) {
        const int nxt = k0 + 32;
        if (nxt < K) {
            load_stage(st ^ 1, nxt);
            CP_COMMIT();
        }

        const float* sA = sAb + st * SA_ST;
        const float* sB = sBb + st * SB_ST;
#pragma unroll
        for (int ks = 0; ks < 4; ks++) {
            const int kb = ks * 8;
            unsigned af[2][4];
#pragma unroll
            for (int mt = 0; mt < 2; mt++) {
                const int row = wm + mt * 16;
                af[mt][0] = __float_as_uint(sA[(row + g    ) * 36 + kb + t    ]);
                af[mt][1] = __float_as_uint(sA[(row + g + 8) * 36 + kb + t    ]);
                af[mt][2] = __float_as_uint(sA[(row + g    ) * 36 + kb + t + 4]);
                af[mt][3] = __float_as_uint(sA[(row + g + 8) * 36 + kb + t + 4]);
            }
            unsigned bf[8][2];
#pragma unroll
            for (int nt = 0; nt < 8; nt++) {
                const int col = wn + nt * 8 + g;
                bf[nt][0] = __float_as_uint(sB[(kb + t    ) * 136 + col]);
                bf[nt][1] = __float_as_uint(sB[(kb + t + 4) * 136 + col]);
            }
#pragma unroll
            for (int mt = 0; mt < 2; mt++)
#pragma unroll
                for (int nt = 0; nt < 8; nt++)
                    mma_tf32(acc[mt][nt], af[mt], bf[nt]);
        }

        if (nxt < K) CP_WAIT0();
        __syncthreads();
        st ^= 1;
    }

#pragma unroll
    for (int mt = 0; mt < 2; mt++) {
#pragma unroll
        for (int nt = 0; nt < 8; nt++) {
            const size_t row = (size_t)(m0 + wm + mt * 16 + g);
            const int    col = n0 + wn + nt * 8 + 2 * t;
            float2 lo = make_float2(acc[mt][nt][0], acc[mt][nt][1]);
            float2 hi = make_float2(acc[mt][nt][2], acc[mt][nt][3]);
            *reinterpret_cast<float2*>(&C[row * N + col])       = lo;
            *reinterpret_cast<float2*>(&C[(row + 8) * N + col]) = hi;
        }
    }
}

// ---------------------------------------------------------------------------
// Fused smolgen attention v6: one block per (b, q). 256 threads, 4 blocks/SM.
// Smem tiles at stride 64 with rotation swizzle (conflict-free, no padding):
//   element (k, d) lives at  k*64 + ((d + 4*k) & 63)
// Single K/V tile (staged K -> logits -> staged V -> output).
// Per-warp redundant softmax; probs distributed via shfl. 4 barriers/head.
// Output written tf32-rounded (feeds Wo GEMM directly).
// ---------------------------------------------------------------------------
#define SWZ(k, d) (((d) + 4*(k)) & 63)

__global__ __launch_bounds__(256, 4) void attn_kernel(
    const float* __restrict__ Q, const float* __restrict__ Kt,
    const float* __restrict__ V,
    const float* __restrict__ AQ, const float* __restrict__ AK,
    const float* __restrict__ AV, float* __restrict__ Out)
{
    extern __shared__ float smem[];
    float* sQ  = smem;                  // 1024
    float* sAk = sQ  + HH * HDD;        // 64*64 swizzled
    float* sAv = sAk + TT * HDD;        // 64*64 swizzled
    float* sKV = sAv + TT * HDD;        // 64*64 swizzled (K then V per head)
    float* sLog = sKV + TT * HDD;       // 64
    float* sRed = sLog + TT;            // 256

    const int tid  = threadIdx.x;
    const int lane = tid & 31;
    const size_t row = (size_t)blockIdx.x;
    const int b = blockIdx.x >> 6;

    const int lk  = tid >> 2;           // 0..63 (logits k index)
    const int lp  = tid & 3;            // 0..3  (logits d-phase)
    const int od  = tid & 63;           // output d index
    const int okp = tid >> 6;           // output k-quarter (warp-uniform)

    // Prologue: Q row; a_k/a_v tiles (swizzled); a_q slice in regs.
    {
        const float4* src = reinterpret_cast<const float4*>(Q + row * DD);
        reinterpret_cast<float4*>(sQ)[tid] = src[tid];
    }
    {
        const float4* k4 = reinterpret_cast<const float4*>(AK + row * TT * HDD);
        const float4* v4 = reinterpret_cast<const float4*>(AV + row * TT * HDD);
#pragma unroll
        for (int r = 0; r < 4; r++) {
            int f  = tid + r * 256;
            int kk = f >> 4;
            int c4 = (f & 15) * 4;
            int so = kk * 64 + SWZ(kk, c4);
            *reinterpret_cast<float4*>(&sAk[so]) = k4[f];
            *reinterpret_cast<float4*>(&sAv[so]) = v4[f];
        }
    }
    float aq_r[16];
    {
        const float* aqp = AQ + row * TT * HDD + lk * HDD + lp;
#pragma unroll
        for (int i = 0; i < 16; i++) aq_r[i] = aqp[4 * i];
    }
    __syncthreads();

    const float* kbB = Kt + (size_t)b * TT * DD;
    const float* vbB = V  + (size_t)b * TT * DD;

    for (int h = 0; h < HH; h++) {
        const int hoff = h * HDD;

        // ---- stage K tile (swizzled) ----
        {
            const float* kb = kbB + hoff;
#pragma unroll
            for (int r = 0; r < 4; r++) {
                int f  = tid + r * 256;
                int kk = f >> 4;
                int c4 = (f & 15) * 4;
                float4 v = *reinterpret_cast<const float4*>(kb + (size_t)kk * DD + c4);
                *reinterpret_cast<float4*>(&sKV[kk * 64 + SWZ(kk, c4)]) = v;
            }
        }
        __syncthreads();                        // 1: K ready

        // ---- logits ----
        {
            const float* qh = sQ + hoff;
            float c = 0.f, bq = 0.f, bk = 0.f;
#pragma unroll
            for (int i = 0; i < 16; i++) {
                int d  = lp + 4 * i;
                int so = lk * 64 + SWZ(lk, d);
                float kv = sKV[so];
                float qv = qh[d];
                c  += qv * kv;
                bq += aq_r[i] * kv;
                bk += qv * sAk[so];
            }
            float l = c * 0.125f + bq + bk;
            l += __shfl_xor_sync(0xffffffffu, l, 1);
            l += __shfl_xor_sync(0xffffffffu, l, 2);
            if (lp == 0) sLog[lk] = l;
        }
        __syncthreads();                        // 2: sLog ready, sKV free

        // ---- per-warp redundant softmax ----
        float p0, p1;
        {
            float a  = sLog[lane];
            float b2 = sLog[lane + 32];
            float m = fmaxf(a, b2);
#pragma unroll
            for (int o = 16; o; o >>= 1)
                m = fmaxf(m, __shfl_xor_sync(0xffffffffu, m, o));
            float ea = __expf(a - m), eb = __expf(b2 - m);
            float s = ea + eb;
#pragma unroll
            for (int o = 16; o; o >>= 1)
                s += __shfl_xor_sync(0xffffffffu, s, o);
            float inv = 1.0f / s;
            p0 = ea * inv;                      // p[lane]
            p1 = eb * inv;                      // p[lane+32]
        }

        // ---- stage V tile into sKV ----
        {
            const float* vb = vbB + hoff;
#pragma unroll
            for (int r = 0; r < 4; r++) {
                int f  = tid + r * 256;
                int kk = f >> 4;
                int c4 = (f & 15) * 4;
                float4 v = *reinterpret_cast<const float4*>(vb + (size_t)kk * DD + c4);
                *reinterpret_cast<float4*>(&sKV[kk * 64 + SWZ(kk, c4)]) = v;
            }
        }
        __syncthreads();                        // 3: V ready

        // ---- output: out[h][od] = sum_k p[k]*(V[k][od] + a_v[k][od]) ----
        {
            float acc = 0.f;
#pragma unroll
            for (int i = 0; i < 16; i++) {
                int k  = okp * 16 + i;
                float pk = __shfl_sync(0xffffffffu, (okp < 2) ? p0 : p1, k & 31);
                int so = k * 64 + SWZ(k, od);
                acc += pk * (sKV[so] + sAv[so]);
            }
            sRed[tid] = acc;
        }
        __syncthreads();                        // 4: sRed ready
        if (tid < 64) {
            float o = sRed[tid] + sRed[tid + 64] + sRed[tid + 128] + sRed[tid + 192];
            Out[row * DD + hoff + tid] = to_tf32(o);
        }
        // next head's K staging (after barrier-1 wait pattern) is safe:
        // all sKV readers finished before barrier 4; sRed readers finish
        // before the next barrier 1.
    }
}

// ---------------------------------------------------------------------------
extern "C" void kernel_launch(void* const* d_in, const int* in_sizes, int n_in,
                              void* d_out, int out_size)
{
    const float* x  = (const float*)d_in[0];
    const float* aq = (const float*)d_in[1];
    const float* ak = (const float*)d_in[2];
    const float* av = (const float*)d_in[3];
    const float* Wq = (const float*)d_in[4];
    const float* Wk = (const float*)d_in[5];
    const float* Wv = (const float*)d_in[6];
    const float* Wo = (const float*)d_in[7];
    float* out = (float*)d_out;

    float *pq, *pk, *pv, *patt, *pxt, *pwt;
    cudaGetSymbolAddress((void**)&pq,   g_q);
    cudaGetSymbolAddress((void**)&pk,   g_k);
    cudaGetSymbolAddress((void**)&pv,   g_v);
    cudaGetSymbolAddress((void**)&patt, g_att);
    cudaGetSymbolAddress((void**)&pxt,  g_xt);
    cudaGetSymbolAddress((void**)&pwt,  g_wt);

    // tf32 pre-round: x and the 4 weight matrices
    const int W_ELEMS = DD * DD;
    cvt_tf32_kernel<<<512, 256>>>(x,  pxt, BT * DD / 4);
    cvt_tf32_kernel<<<128, 256>>>(Wq, pwt + 0 * W_ELEMS, W_ELEMS / 4);
    cvt_tf32_kernel<<<128, 256>>>(Wk, pwt + 1 * W_ELEMS, W_ELEMS / 4);
    cvt_tf32_kernel<<<128, 256>>>(Wv, pwt + 2 * W_ELEMS, W_ELEMS / 4);
    cvt_tf32_kernel<<<128, 256>>>(Wo, pwt + 3 * W_ELEMS, W_ELEMS / 4);

    cudaFuncSetAttribute((const void*)tf32_gemm_kernel,
                         cudaFuncAttributeMaxDynamicSharedMemorySize, GEMM_SMEM);

    // fused QKV projections
    dim3 qkv_grid(DD / 128, BT / 128, 3);
    tf32_gemm_kernel<<<qkv_grid, 256, GEMM_SMEM>>>(
        pxt, pwt + 0 * W_ELEMS, pwt + 1 * W_ELEMS, pwt + 2 * W_ELEMS,
        pq, pk, pv, BT, DD, DD);

    const int smem_bytes = (HH*HDD + 3 * TT * HDD + TT + 256) * (int)sizeof(float);
    cudaFuncSetAttribute((const void*)attn_kernel,
                         cudaFuncAttributeMaxDynamicSharedMemorySize, smem_bytes);
    attn_kernel<<<BT, 256, smem_bytes>>>(pq, pk, pv, aq, ak, av, patt);

    dim3 o_grid(DD / 128, BT / 128, 1);
    tf32_gemm_kernel<<<o_grid, 256, GEMM_SMEM>>>(
        patt, pwt + 3 * W_ELEMS, pwt + 3 * W_ELEMS, pwt + 3 * W_ELEMS,
        out, out, out, BT, DD, DD);
}

// round 7
// speedup vs baseline: 1.2244x; 1.1222x over previous
#include <cuda_runtime.h>
#include <cuda_bf16.h>
#include <cuda_fp16.h>
#include <math.h>

// Problem constants
#define BB 128
#define TT 64
#define DD 1024
#define HH 16
#define HDD 64
#define BT (BB*TT)        // 8192

// Scratch (device globals: allocation-free rule)
__device__ float g_q[BT*DD];
__device__ float g_k[BT*DD];
__device__ float g_v[BT*DD];
__device__ float g_att[BT*DD];
__device__ float g_xt[BT*DD];       // tf32-rounded x
__device__ float g_wt[4*DD*DD];     // tf32-rounded Wq,Wk,Wv,Wo

__device__ __forceinline__ float to_tf32(float x) {
    float r;
    asm("cvt.rna.tf32.f32 %0, %1;" : "=f"(r) : "f"(x));
    return r;
}

__device__ __forceinline__ void mma_tf32(float c[4], const unsigned a[4], const unsigned b[2]) {
    asm volatile(
        "mma.sync.aligned.m16n8k8.row.col.f32.tf32.tf32.f32 "
        "{%0,%1,%2,%3}, {%4,%5,%6,%7}, {%8,%9}, {%0,%1,%2,%3};"
        : "+f"(c[0]), "+f"(c[1]), "+f"(c[2]), "+f"(c[3])
        : "r"(a[0]), "r"(a[1]), "r"(a[2]), "r"(a[3]),
          "r"(b[0]), "r"(b[1]));
}

__device__ __forceinline__ void cp_async16(void* smem, const void* gmem) {
    unsigned s = (unsigned)__cvta_generic_to_shared(smem);
    asm volatile("cp.async.cg.shared.global [%0], [%1], 16;\n" :: "r"(s), "l"(gmem));
}
#define CP_COMMIT() asm volatile("cp.async.commit_group;\n" ::: "memory")
#define CP_WAIT0()  asm volatile("cp.async.wait_group 0;\n" ::: "memory")

// ---------------------------------------------------------------------------
// tf32 pre-round pass
// ---------------------------------------------------------------------------
__global__ __launch_bounds__(256) void cvt_tf32_kernel(
    const float* __restrict__ src, float* __restrict__ dst, int n4)
{
    int i = blockIdx.x * blockDim.x + threadIdx.x;
    int stride = gridDim.x * blockDim.x;
    const float4* s4 = reinterpret_cast<const float4*>(src);
    float4* d4 = reinterpret_cast<float4*>(dst);
    for (; i < n4; i += stride) {
        float4 v = s4[i];
        v.x = to_tf32(v.x); v.y = to_tf32(v.y);
        v.z = to_tf32(v.z); v.w = to_tf32(v.w);
        d4[i] = v;
    }
}

// ---------------------------------------------------------------------------
// TF32 tensor-core GEMM (unchanged from R6): pre-rounded inputs, cp.async
// double buffer. blockIdx.z selects among W0..2 / C0..2.
// ---------------------------------------------------------------------------
#define SA_ST 4608   // 128*36
#define SB_ST 4352   // 32*136
#define GEMM_SMEM ((2*SA_ST + 2*SB_ST) * 4)

__global__ __launch_bounds__(256) void tf32_gemm_kernel(
    const float* __restrict__ A,
    const float* __restrict__ W0, const float* __restrict__ W1,
    const float* __restrict__ W2,
    float* __restrict__ C0, float* __restrict__ C1, float* __restrict__ C2,
    int M, int N, int K)
{
    extern __shared__ float dsm[];
    float* sAb = dsm;
    float* sBb = dsm + 2 * SA_ST;

    const float* W = (blockIdx.z == 0) ? W0 : (blockIdx.z == 1) ? W1 : W2;
    float*       C = (blockIdx.z == 0) ? C0 : (blockIdx.z == 1) ? C1 : C2;

    const int tid  = threadIdx.x;
    const int lane = tid & 31;
    const int wid  = tid >> 5;
    const int wm   = (wid & 3) * 32;
    const int wn   = (wid >> 2) * 64;
    const int g    = lane >> 2;
    const int t    = lane & 3;

    const int m0 = blockIdx.y * 128;
    const int n0 = blockIdx.x * 128;

    float acc[2][8][4];
#pragma unroll
    for (int mt = 0; mt < 2; mt++)
#pragma unroll
        for (int nt = 0; nt < 8; nt++)
#pragma unroll
            for (int i = 0; i < 4; i++) acc[mt][nt][i] = 0.f;

    auto load_stage = [&](int st, int k0) {
        float* sA = sAb + st * SA_ST;
        float* sB = sBb + st * SB_ST;
#pragma unroll
        for (int r = 0; r < 4; r++) {
            int f   = tid + r * 256;
            int row = f >> 3;
            int c4  = (f & 7) * 4;
            cp_async16(&sA[row * 36 + c4],
                       &A[(size_t)(m0 + row) * K + k0 + c4]);
        }
#pragma unroll
        for (int r = 0; r < 4; r++) {
            int f   = tid + r * 256;
            int row = f >> 5;
            int c4  = (f & 31) * 4;
            cp_async16(&sB[row * 136 + c4],
                       &W[(size_t)(k0 + row) * N + n0 + c4]);
        }
    };

    load_stage(0, 0);
    CP_COMMIT();
    CP_WAIT0();
    __syncthreads();

    int st = 0;
    for (int k0 = 0; k0 < K; k0 += 32) {
        const int nxt = k0 + 32;
        if (nxt < K) {
            load_stage(st ^ 1, nxt);
            CP_COMMIT();
        }

        const float* sA = sAb + st * SA_ST;
        const float* sB = sBb + st * SB_ST;
#pragma unroll
        for (int ks = 0; ks < 4; ks++) {
            const int kb = ks * 8;
            unsigned af[2][4];
#pragma unroll
            for (int mt = 0; mt < 2; mt++) {
                const int row = wm + mt * 16;
                af[mt][0] = __float_as_uint(sA[(row + g    ) * 36 + kb + t    ]);
                af[mt][1] = __float_as_uint(sA[(row + g + 8) * 36 + kb + t    ]);
                af[mt][2] = __float_as_uint(sA[(row + g    ) * 36 + kb + t + 4]);
                af[mt][3] = __float_as_uint(sA[(row + g + 8) * 36 + kb + t + 4]);
            }
            unsigned bf[8][2];
#pragma unroll
            for (int nt = 0; nt < 8; nt++) {
                const int col = wn + nt * 8 + g;
                bf[nt][0] = __float_as_uint(sB[(kb + t    ) * 136 + col]);
                bf[nt][1] = __float_as_uint(sB[(kb + t + 4) * 136 + col]);
            }
#pragma unroll
            for (int mt = 0; mt < 2; mt++)
#pragma unroll
                for (int nt = 0; nt < 8; nt++)
                    mma_tf32(acc[mt][nt], af[mt], bf[nt]);
        }

        if (nxt < K) CP_WAIT0();
        __syncthreads();
        st ^= 1;
    }

#pragma unroll
    for (int mt = 0; mt < 2; mt++) {
#pragma unroll
        for (int nt = 0; nt < 8; nt++) {
            const size_t row = (size_t)(m0 + wm + mt * 16 + g);
            const int    col = n0 + wn + nt * 8 + 2 * t;
            float2 lo = make_float2(acc[mt][nt][0], acc[mt][nt][1]);
            float2 hi = make_float2(acc[mt][nt][2], acc[mt][nt][3]);
            *reinterpret_cast<float2*>(&C[row * N + col])       = lo;
            *reinterpret_cast<float2*>(&C[(row + 8) * N + col]) = hi;
        }
    }
}

// ---------------------------------------------------------------------------
// Fused smolgen attention v7: one block per (b, q-pair). 512 threads,
// 2 blocks/SM. K/V double-buffered via cp.async (overlap with compute);
// a_k/a_v tiles in fp16 smem; a_q in regs. Rotation swizzle (d + 4k) & 63.
// 3 barriers per head.
// ---------------------------------------------------------------------------
#define SWZ(k, d) (((d) + 4*(k)) & 63)

// smem float offsets
#define SQ_OFF    0                      // float[2][1024]
#define SKV_OFF   2048                   // float[2buf][2 (K,V)][64][64]
#define SAK_OFF   (2048 + 16384)         // half [2][64][64] => 4096 floats
#define SAV_OFF   (SAK_OFF + 4096)       // half [2][64][64]
#define SLOG_OFF  (SAV_OFF + 4096)       // float[2][64]
#define SRED_OFF  (SLOG_OFF + 128)       // float[512]
#define ATTN_SMEM ((SRED_OFF + 512) * 4) // bytes = 109056

__global__ __launch_bounds__(512, 2) void attn_kernel(
    const float* __restrict__ Q, const float* __restrict__ Kt,
    const float* __restrict__ V,
    const float* __restrict__ AQ, const float* __restrict__ AK,
    const float* __restrict__ AV, float* __restrict__ Out)
{
    extern __shared__ float smem[];
    float*  sQ   = smem + SQ_OFF;
    float*  sKV  = smem + SKV_OFF;
    __half* sAk  = reinterpret_cast<__half*>(smem + SAK_OFF);
    __half* sAv  = reinterpret_cast<__half*>(smem + SAV_OFF);
    float*  sLog = smem + SLOG_OFF;
    float*  sRed = smem + SRED_OFF;

    const int t    = threadIdx.x;
    const int lane = t & 31;
    const int b    = blockIdx.x >> 5;
    const int qg   = blockIdx.x & 31;
    const int row0 = b * TT + qg * 2;          // first of 2 q rows

    const int qp   = t >> 8;                   // 0..1 (q' index)
    const int loc  = t & 255;
    const int lk   = loc >> 2;                 // 0..63
    const int lp   = loc & 3;                  // 0..3
    const int od   = loc & 63;
    const int okp  = loc >> 6;                 // 0..3

    // ---- prologue ----
    // sQ: 2 contiguous Q rows (2048 floats = 512 float4)
    reinterpret_cast<float4*>(sQ)[t] =
        reinterpret_cast<const float4*>(Q + (size_t)row0 * DD)[t];

    // sAk/sAv: 2 q rows each, fp32 -> fp16, swizzled
#pragma unroll
    for (int r = 0; r < 8; r++) {
        int c   = t + r * 512;                 // 0..4095 float4 chunks
        int ten = c >> 11;                     // 0 = AK, 1 = AV
        int rem = c & 2047;
        int qq  = rem >> 10;
        int rm2 = rem & 1023;
        int kk  = rm2 >> 4;
        int d4  = (rm2 & 15) * 4;
        const float* src = (ten ? AV : AK) +
            (((size_t)(row0 + qq)) * TT + kk) * HDD + d4;
        float4 v = *reinterpret_cast<const float4*>(src);
        __half2 h01 = __floats2half2_rn(v.x, v.y);
        __half2 h23 = __floats2half2_rn(v.z, v.w);
        uint2 packed;
        packed.x = *reinterpret_cast<unsigned*>(&h01);
        packed.y = *reinterpret_cast<unsigned*>(&h23);
        __half* dst = (ten ? sAv : sAk) + qq * 4096 + kk * 64 + SWZ(kk, d4);
        *reinterpret_cast<uint2*>(dst) = packed;
    }

    // a_q slice -> registers (16 values: d = lp + 4i for this (qp, lk))
    float aq_r[16];
    {
        const float* aqp = AQ + (((size_t)(row0 + qp)) * TT + lk) * HDD + lp;
#pragma unroll
        for (int i = 0; i < 16; i++) aq_r[i] = aqp[4 * i];
    }

    // initial K/V stage for head 0 into buffer 0
    const float* kbB = Kt + (size_t)b * TT * DD;
    const float* vbB = V  + (size_t)b * TT * DD;

    auto stage_kv = [&](int buf, int h) {
        const int hoff = h * HDD;
#pragma unroll
        for (int r = 0; r < 4; r++) {
            int c   = t + r * 512;             // 0..2047 float4 chunks
            int ten = c >> 10;                 // 0 = K, 1 = V
            int rem = c & 1023;
            int kk  = rem >> 4;
            int d4  = (rem & 15) * 4;
            const float* src = (ten ? vbB : kbB) +
                (size_t)kk * DD + hoff + d4;
            cp_async16(&sKV[buf * 8192 + ten * 4096 + kk * 64 + SWZ(kk, d4)], src);
        }
    };

    stage_kv(0, 0);
    CP_COMMIT();
    CP_WAIT0();
    __syncthreads();

    int cur = 0;
    for (int h = 0; h < HH; h++) {
        const int hoff = h * HDD;

        // prefetch next head's K/V into the other buffer
        if (h + 1 < HH) {
            stage_kv(cur ^ 1, h + 1);
            CP_COMMIT();
        }

        // ---- logits ----
        {
            const float*  qh = sQ + qp * DD + hoff;
            const float*  kp = sKV + cur * 8192;              // K part
            const __half* ap = sAk + qp * 4096;
            float c = 0.f, bq = 0.f, bk = 0.f;
#pragma unroll
            for (int i = 0; i < 16; i++) {
                int d  = lp + 4 * i;
                int so = lk * 64 + SWZ(lk, d);
                float kv = kp[so];
                float qv = qh[d];
                c  += qv * kv;
                bq += aq_r[i] * kv;
                bk += qv * __half2float(ap[so]);
            }
            float l = c * 0.125f + bq + bk;
            l += __shfl_xor_sync(0xffffffffu, l, 1);
            l += __shfl_xor_sync(0xffffffffu, l, 2);
            if (lp == 0) sLog[qp * 64 + lk] = l;
        }
        __syncthreads();                       // 1: sLog ready

        // ---- per-warp redundant softmax (warp's qp is uniform) ----
        float p0, p1;
        {
            float a  = sLog[qp * 64 + lane];
            float b2 = sLog[qp * 64 + lane + 32];
            float m = fmaxf(a, b2);
#pragma unroll
            for (int o = 16; o; o >>= 1)
                m = fmaxf(m, __shfl_xor_sync(0xffffffffu, m, o));
            float ea = __expf(a - m), eb = __expf(b2 - m);
            float s = ea + eb;
#pragma unroll
            for (int o = 16; o; o >>= 1)
                s += __shfl_xor_sync(0xffffffffu, s, o);
            float inv = 1.0f / s;
            p0 = ea * inv;
            p1 = eb * inv;
        }

        // ---- output partials ----
        {
            const float*  vp = sKV + cur * 8192 + 4096;       // V part
            const __half* ap = sAv + qp * 4096;
            float acc = 0.f;
#pragma unroll
            for (int i = 0; i < 16; i++) {
                int k  = okp * 16 + i;
                float pk = __shfl_sync(0xffffffffu, (okp < 2) ? p0 : p1, k & 31);
                int so = k * 64 + SWZ(k, od);
                acc += pk * (vp[so] + __half2float(ap[so]));
            }
            sRed[t] = acc;
        }
        __syncthreads();                       // 2: sRed ready

        if (t < 128) {
            int qq  = t >> 6;
            int dd2 = t & 63;
            int base = qq * 256 + dd2;
            float o = sRed[base] + sRed[base + 64] + sRed[base + 128] + sRed[base + 192];
            Out[(size_t)(row0 + qq) * DD + hoff + dd2] = to_tf32(o);
        }

        CP_WAIT0();
        __syncthreads();                       // 3: next KV in, sRed/sLog free
        cur ^= 1;
    }
}

// ---------------------------------------------------------------------------
extern "C" void kernel_launch(void* const* d_in, const int* in_sizes, int n_in,
                              void* d_out, int out_size)
{
    const float* x  = (const float*)d_in[0];
    const float* aq = (const float*)d_in[1];
    const float* ak = (const float*)d_in[2];
    const float* av = (const float*)d_in[3];
    const float* Wq = (const float*)d_in[4];
    const float* Wk = (const float*)d_in[5];
    const float* Wv = (const float*)d_in[6];
    const float* Wo = (const float*)d_in[7];
    float* out = (float*)d_out;

    float *pq, *pk, *pv, *patt, *pxt, *pwt;
    cudaGetSymbolAddress((void**)&pq,   g_q);
    cudaGetSymbolAddress((void**)&pk,   g_k);
    cudaGetSymbolAddress((void**)&pv,   g_v);
    cudaGetSymbolAddress((void**)&patt, g_att);
    cudaGetSymbolAddress((void**)&pxt,  g_xt);
    cudaGetSymbolAddress((void**)&pwt,  g_wt);

    const int W_ELEMS = DD * DD;
    cvt_tf32_kernel<<<512, 256>>>(x,  pxt, BT * DD / 4);
    cvt_tf32_kernel<<<128, 256>>>(Wq, pwt + 0 * W_ELEMS, W_ELEMS / 4);
    cvt_tf32_kernel<<<128, 256>>>(Wk, pwt + 1 * W_ELEMS, W_ELEMS / 4);
    cvt_tf32_kernel<<<128, 256>>>(Wv, pwt + 2 * W_ELEMS, W_ELEMS / 4);
    cvt_tf32_kernel<<<128, 256>>>(Wo, pwt + 3 * W_ELEMS, W_ELEMS / 4);

    cudaFuncSetAttribute((const void*)tf32_gemm_kernel,
                         cudaFuncAttributeMaxDynamicSharedMemorySize, GEMM_SMEM);

    dim3 qkv_grid(DD / 128, BT / 128, 3);
    tf32_gemm_kernel<<<qkv_grid, 256, GEMM_SMEM>>>(
        pxt, pwt + 0 * W_ELEMS, pwt + 1 * W_ELEMS, pwt + 2 * W_ELEMS,
        pq, pk, pv, BT, DD, DD);

    cudaFuncSetAttribute((const void*)attn_kernel,
                         cudaFuncAttributeMaxDynamicSharedMemorySize, ATTN_SMEM);
    attn_kernel<<<BB * 32, 512, ATTN_SMEM>>>(pq, pk, pv, aq, ak, av, patt);

    dim3 o_grid(DD / 128, BT / 128, 1);
    tf32_gemm_kernel<<<o_grid, 256, GEMM_SMEM>>>(
        patt, pwt + 3 * W_ELEMS, pwt + 3 * W_ELEMS, pwt + 3 * W_ELEMS,
        out, out, out, BT, DD, DD);
}

// round 9
// speedup vs baseline: 1.5297x; 1.2493x over previous
#include <cuda_runtime.h>
#include <cuda_bf16.h>
#include <cuda_fp16.h>
#include <math.h>

// Problem constants
#define BB 128
#define TT 64
#define DD 1024
#define HH 16
#define HDD 64
#define BT (BB*TT)        // 8192

// Scratch (device globals: allocation-free rule)
__device__ float  g_q[BT*DD];
__device__ __half g_kh[BT*DD];
__device__ __half g_vh[BT*DD];
__device__ float  g_att[BT*DD];
__device__ float  g_xt[BT*DD];       // tf32-rounded x
__device__ float  g_wt[4*DD*DD];     // tf32-rounded Wq,Wk,Wv,Wo

__device__ __forceinline__ float to_tf32(float x) {
    float r;
    asm("cvt.rna.tf32.f32 %0, %1;" : "=f"(r) : "f"(x));
    return r;
}

__device__ __forceinline__ void mma_tf32(float c[4], const unsigned a[4], const unsigned b[2]) {
    asm volatile(
        "mma.sync.aligned.m16n8k8.row.col.f32.tf32.tf32.f32 "
        "{%0,%1,%2,%3}, {%4,%5,%6,%7}, {%8,%9}, {%0,%1,%2,%3};"
        : "+f"(c[0]), "+f"(c[1]), "+f"(c[2]), "+f"(c[3])
        : "r"(a[0]), "r"(a[1]), "r"(a[2]), "r"(a[3]),
          "r"(b[0]), "r"(b[1]));
}

__device__ __forceinline__ void cp_async16(void* smem, const void* gmem) {
    unsigned s = (unsigned)__cvta_generic_to_shared(smem);
    asm volatile("cp.async.cg.shared.global [%0], [%1], 16;\n" :: "r"(s), "l"(gmem));
}
#define CP_COMMIT() asm volatile("cp.async.commit_group;\n" ::: "memory")
#define CP_WAIT0()  asm volatile("cp.async.wait_group 0;\n" ::: "memory")

// ---------------------------------------------------------------------------
// tf32 pre-round pass
// ---------------------------------------------------------------------------
__global__ __launch_bounds__(256) void cvt_tf32_kernel(
    const float* __restrict__ src, float* __restrict__ dst, int n4)
{
    int i = blockIdx.x * blockDim.x + threadIdx.x;
    int stride = gridDim.x * blockDim.x;
    const float4* s4 = reinterpret_cast<const float4*>(src);
    float4* d4 = reinterpret_cast<float4*>(dst);
    for (; i < n4; i += stride) {
        float4 v = s4[i];
        v.x = to_tf32(v.x); v.y = to_tf32(v.y);
        v.z = to_tf32(v.z); v.w = to_tf32(v.w);
        d4[i] = v;
    }
}

// ---------------------------------------------------------------------------
// TF32 tensor-core GEMM: pre-rounded inputs, cp.async double buffer.
// blockIdx.z selects W/C; if H[z] != null the output is written fp16.
// ---------------------------------------------------------------------------
#define SA_ST 4608   // 128*36
#define SB_ST 4352   // 32*136
#define GEMM_SMEM ((2*SA_ST + 2*SB_ST) * 4)

__global__ __launch_bounds__(256) void tf32_gemm_kernel(
    const float* __restrict__ A,
    const float* __restrict__ W0, const float* __restrict__ W1,
    const float* __restrict__ W2,
    float* __restrict__ C0, float* __restrict__ C1, float* __restrict__ C2,
    __half* __restrict__ H0, __half* __restrict__ H1, __half* __restrict__ H2,
    int M, int N, int K)
{
    extern __shared__ float dsm[];
    float* sAb = dsm;
    float* sBb = dsm + 2 * SA_ST;

    const float* W = (blockIdx.z == 0) ? W0 : (blockIdx.z == 1) ? W1 : W2;
    float*       C = (blockIdx.z == 0) ? C0 : (blockIdx.z == 1) ? C1 : C2;
    __half*      Hp = (blockIdx.z == 0) ? H0 : (blockIdx.z == 1) ? H1 : H2;

    const int tid  = threadIdx.x;
    const int lane = tid & 31;
    const int wid  = tid >> 5;
    const int wm   = (wid & 3) * 32;
    const int wn   = (wid >> 2) * 64;
    const int g    = lane >> 2;
    const int t    = lane & 3;

    const int m0 = blockIdx.y * 128;
    const int n0 = blockIdx.x * 128;

    float acc[2][8][4];
#pragma unroll
    for (int mt = 0; mt < 2; mt++)
#pragma unroll
        for (int nt = 0; nt < 8; nt++)
#pragma unroll
            for (int i = 0; i < 4; i++) acc[mt][nt][i] = 0.f;

    auto load_stage = [&](int st, int k0) {
        float* sA = sAb + st * SA_ST;
        float* sB = sBb + st * SB_ST;
#pragma unroll
        for (int r = 0; r < 4; r++) {
            int f   = tid + r * 256;
            int row = f >> 3;
            int c4  = (f & 7) * 4;
            cp_async16(&sA[row * 36 + c4],
                       &A[(size_t)(m0 + row) * K + k0 + c4]);
        }
#pragma unroll
        for (int r = 0; r < 4; r++) {
            int f   = tid + r * 256;
            int row = f >> 5;
            int c4  = (f & 31) * 4;
            cp_async16(&sB[row * 136 + c4],
                       &W[(size_t)(k0 + row) * N + n0 + c4]);
        }
    };

    load_stage(0, 0);
    CP_COMMIT();
    CP_WAIT0();
    __syncthreads();

    int st = 0;
    for (int k0 = 0; k0 < K; k0 += 32) {
        const int nxt = k0 + 32;
        if (nxt < K) {
            load_stage(st ^ 1, nxt);
            CP_COMMIT();
        }

        const float* sA = sAb + st * SA_ST;
        const float* sB = sBb + st * SB_ST;
#pragma unroll
        for (int ks = 0; ks < 4; ks++) {
            const int kb = ks * 8;
            unsigned af[2][4];
#pragma unroll
            for (int mt = 0; mt < 2; mt++) {
                const int row = wm + mt * 16;
                af[mt][0] = __float_as_uint(sA[(row + g    ) * 36 + kb + t    ]);
                af[mt][1] = __float_as_uint(sA[(row + g + 8) * 36 + kb + t    ]);
                af[mt][2] = __float_as_uint(sA[(row + g    ) * 36 + kb + t + 4]);
                af[mt][3] = __float_as_uint(sA[(row + g + 8) * 36 + kb + t + 4]);
            }
            unsigned bf[8][2];
#pragma unroll
            for (int nt = 0; nt < 8; nt++) {
                const int col = wn + nt * 8 + g;
                bf[nt][0] = __float_as_uint(sB[(kb + t    ) * 136 + col]);
                bf[nt][1] = __float_as_uint(sB[(kb + t + 4) * 136 + col]);
            }
#pragma unroll
            for (int mt = 0; mt < 2; mt++)
#pragma unroll
                for (int nt = 0; nt < 8; nt++)
                    mma_tf32(acc[mt][nt], af[mt], bf[nt]);
        }

        if (nxt < K) CP_WAIT0();
        __syncthreads();
        st ^= 1;
    }

#pragma unroll
    for (int mt = 0; mt < 2; mt++) {
#pragma unroll
        for (int nt = 0; nt < 8; nt++) {
            const size_t row = (size_t)(m0 + wm + mt * 16 + g);
            const int    col = n0 + wn + nt * 8 + 2 * t;
            if (Hp) {
                __half2 lo = __floats2half2_rn(acc[mt][nt][0], acc[mt][nt][1]);
                __half2 hi = __floats2half2_rn(acc[mt][nt][2], acc[mt][nt][3]);
                *reinterpret_cast<__half2*>(&Hp[row * N + col])       = lo;
                *reinterpret_cast<__half2*>(&Hp[(row + 8) * N + col]) = hi;
            } else {
                float2 lo = make_float2(acc[mt][nt][0], acc[mt][nt][1]);
                float2 hi = make_float2(acc[mt][nt][2], acc[mt][nt][3]);
                *reinterpret_cast<float2*>(&C[row * N + col])       = lo;
                *reinterpret_cast<float2*>(&C[(row + 8) * N + col]) = hi;
            }
        }
    }
}

// ---------------------------------------------------------------------------
// Fused smolgen attention v8: block per (b, q-pair), 512 threads, 2 blk/SM.
// K/V fp16 in gmem; K/V + a_k/a_v fp16 in smem; half2 inner loops.
// Rotation swizzle in half2 units: SWZ2(k,d2) = (d2 + 4k) & 31
// (conflict-free for logits (lk, lp+4i) and output (okp, od2); 16B-aligned).
// ---------------------------------------------------------------------------
#define SWZ2(k, d2) (((d2) + 4*(k)) & 31)

// smem float offsets
#define SQ_OFF    0                       // float[2][1024]
#define SKV_OFF   2048                    // half[2buf][2(K,V)][4096]  = 8192 floats
#define SAK_OFF   (2048 + 8192)           // half[2][4096] = 4096 floats
#define SAV_OFF   (SAK_OFF + 4096)        // half[2][4096]
#define SLOG_OFF  (SAV_OFF + 4096)        // float[2][64]
#define SRED_OFF  (SLOG_OFF + 128)        // float[1024]  (2q x 8okp x 64d)
#define ATTN_SMEM ((SRED_OFF + 1024) * 4) // 78336 bytes

__global__ __launch_bounds__(512, 2) void attn_kernel(
    const float* __restrict__ Q, const __half* __restrict__ Kt,
    const __half* __restrict__ V,
    const float* __restrict__ AQ, const float* __restrict__ AK,
    const float* __restrict__ AV, float* __restrict__ Out)
{
    extern __shared__ float smem[];
    float*   sQ   = smem + SQ_OFF;
    __half2* sKV  = reinterpret_cast<__half2*>(smem + SKV_OFF);  // [2buf][2][64][32]
    __half2* sAk  = reinterpret_cast<__half2*>(smem + SAK_OFF);  // [2q][64][32]
    __half2* sAv  = reinterpret_cast<__half2*>(smem + SAV_OFF);
    float*   sLog = smem + SLOG_OFF;
    float*   sRed = smem + SRED_OFF;

    const int t    = threadIdx.x;
    const int lane = t & 31;
    const int b    = blockIdx.x >> 5;
    const int qg   = blockIdx.x & 31;
    const int row0 = b * TT + qg * 2;

    const int qp   = t >> 8;                   // 0..1
    const int loc  = t & 255;
    const int lk   = loc >> 2;                 // 0..63
    const int lp   = loc & 3;                  // 0..3
    const int od2  = loc & 31;                 // 0..31 (half2 d index)
    const int okp  = loc >> 5;                 // 0..7  (k-octile, warp-uniform)

    // ---- prologue ----
    reinterpret_cast<float4*>(sQ)[t] =
        reinterpret_cast<const float4*>(Q + (size_t)row0 * DD)[t];

    // a_k / a_v: fp32 gmem -> fp16 swizzled smem (4096 float4 total)
#pragma unroll
    for (int r = 0; r < 8; r++) {
        int c   = t + r * 512;                 // 0..4095
        int ten = c >> 11;                     // 0=AK 1=AV
        int rem = c & 2047;
        int qq  = rem >> 10;
        int rm2 = rem & 1023;
        int kk  = rm2 >> 4;
        int j   = rm2 & 15;                    // float4 -> d = 4j, d2 = 2j,2j+1
        const float* src = (ten ? AV : AK) +
            (((size_t)(row0 + qq)) * TT + kk) * HDD + 4 * j;
        float4 v = *reinterpret_cast<const float4*>(src);
        uint2 packed;
        {
            __half2 h01 = __floats2half2_rn(v.x, v.y);
            __half2 h23 = __floats2half2_rn(v.z, v.w);
            packed.x = *reinterpret_cast<unsigned*>(&h01);
            packed.y = *reinterpret_cast<unsigned*>(&h23);
        }
        // d2 base 2j: swizzled index even and <31 => the pair stays contiguous
        __half2* dst = (ten ? sAv : sAk) + qq * 2048 + kk * 32 + SWZ2(kk, 2 * j);
        *reinterpret_cast<uint2*>(dst) = packed;
    }

    // a_q slice -> registers: float2 at d2 = lp + 4i
    float2 aq_r[8];
    {
        const float* aqp = AQ + (((size_t)(row0 + qp)) * TT + lk) * HDD + 2 * lp;
#pragma unroll
        for (int i = 0; i < 8; i++)
            aq_r[i] = *reinterpret_cast<const float2*>(aqp + 8 * i);
    }

    const __half* khB = Kt + (size_t)b * TT * DD;
    const __half* vhB = V  + (size_t)b * TT * DD;

    // stage K+V (fp16) for head h into buffer buf: 1024 x 16B chunks
    auto stage_kv = [&](int buf, int h) {
        const int hoff = h * HDD;
#pragma unroll
        for (int r = 0; r < 2; r++) {
            int c   = t + r * 512;             // 0..1023
            int ten = c >> 9;                  // 0=K 1=V
            int rem = c & 511;
            int kk  = rem >> 3;
            int j   = rem & 7;                 // 16B chunk: 8 halves, d2 base 4j
            const __half* src = (ten ? vhB : khB) + (size_t)kk * DD + hoff + 8 * j;
            __half2* dst = sKV + buf * 4096 + ten * 2048 + kk * 32 + SWZ2(kk, 4 * j);
            cp_async16(dst, src);
        }
    };

    stage_kv(0, 0);
    CP_COMMIT();
    CP_WAIT0();
    __syncthreads();

    int cur = 0;
    for (int h = 0; h < HH; h++) {
        const int hoff = h * HDD;

        if (h + 1 < HH) {
            stage_kv(cur ^ 1, h + 1);
            CP_COMMIT();
        }

        // ---- logits (half2 datapath) ----
        {
            const float2*  qh = reinterpret_cast<const float2*>(sQ + qp * DD + hoff);
            const __half2* kp = sKV + cur * 4096;              // K part
            const __half2* ap = sAk + qp * 2048;
            float c = 0.f, bq = 0.f, bk = 0.f;
#pragma unroll
            for (int i = 0; i < 8; i++) {
                int d2 = lp + 4 * i;
                int so = lk * 32 + SWZ2(lk, d2);
                float2 kv = __half22float2(kp[so]);
                float2 ak2 = __half22float2(ap[so]);
                float2 qv = qh[d2];
                c  += qv.x * kv.x + qv.y * kv.y;
                bq += aq_r[i].x * kv.x + aq_r[i].y * kv.y;
                bk += qv.x * ak2.x + qv.y * ak2.y;
            }
            float l = c * 0.125f + bq + bk;
            l += __shfl_xor_sync(0xffffffffu, l, 1);
            l += __shfl_xor_sync(0xffffffffu, l, 2);
            if (lp == 0) sLog[qp * 64 + lk] = l;
        }
        __syncthreads();                       // 1: sLog ready

        // ---- per-warp redundant softmax ----
        float p0, p1;
        {
            float a  = sLog[qp * 64 + lane];
            float b2 = sLog[qp * 64 + lane + 32];
            float m = fmaxf(a, b2);
#pragma unroll
            for (int o = 16; o; o >>= 1)
                m = fmaxf(m, __shfl_xor_sync(0xffffffffu, m, o));
            float ea = __expf(a - m), eb = __expf(b2 - m);
            float s = ea + eb;
#pragma unroll
            for (int o = 16; o; o >>= 1)
                s += __shfl_xor_sync(0xffffffffu, s, o);
            float inv = 1.0f / s;
            p0 = ea * inv;
            p1 = eb * inv;
        }

        // ---- output partials (half2) ----
        {
            const __half2* vp = sKV + cur * 4096 + 2048;       // V part
            const __half2* ap = sAv + qp * 2048;
            float2 acc = make_float2(0.f, 0.f);
#pragma unroll
            for (int i = 0; i < 8; i++) {
                int k  = okp * 8 + i;
                float pk = __shfl_sync(0xffffffffu, (okp < 4) ? p0 : p1, k & 31);
                int so = k * 32 + SWZ2(k, od2);
                float2 vv = __half22float2(vp[so]);
                float2 av2 = __half22float2(ap[so]);
                acc.x += pk * (vv.x + av2.x);
                acc.y += pk * (vv.y + av2.y);
            }
            reinterpret_cast<float2*>(sRed)[(qp * 8 + okp) * 32 + od2] = acc;
        }
        __syncthreads();                       // 2: sRed ready

        if (t < 128) {
            int qq = t >> 6;
            int dd = t & 63;
            const float* rp = sRed + qq * 512 + dd;
            float o = rp[0] + rp[64] + rp[128] + rp[192]
                    + rp[256] + rp[320] + rp[384] + rp[448];
            Out[(size_t)(row0 + qq) * DD + hoff + dd] = to_tf32(o);
        }

        CP_WAIT0();
        __syncthreads();                       // 3: next KV landed, sRed free
        cur ^= 1;
    }
}

// ---------------------------------------------------------------------------
extern "C" void kernel_launch(void* const* d_in, const int* in_sizes, int n_in,
                              void* d_out, int out_size)
{
    const float* x  = (const float*)d_in[0];
    const float* aq = (const float*)d_in[1];
    const float* ak = (const float*)d_in[2];
    const float* av = (const float*)d_in[3];
    const float* Wq = (const float*)d_in[4];
    const float* Wk = (const float*)d_in[5];
    const float* Wv = (const float*)d_in[6];
    const float* Wo = (const float*)d_in[7];
    float* out = (float*)d_out;

    float *pq, *patt, *pxt, *pwt;
    __half *pkh, *pvh;
    cudaGetSymbolAddress((void**)&pq,   g_q);
    cudaGetSymbolAddress((void**)&pkh,  g_kh);
    cudaGetSymbolAddress((void**)&pvh,  g_vh);
    cudaGetSymbolAddress((void**)&patt, g_att);
    cudaGetSymbolAddress((void**)&pxt,  g_xt);
    cudaGetSymbolAddress((void**)&pwt,  g_wt);

    const int W_ELEMS = DD * DD;
    cvt_tf32_kernel<<<512, 256>>>(x,  pxt, BT * DD / 4);
    cvt_tf32_kernel<<<128, 256>>>(Wq, pwt + 0 * W_ELEMS, W_ELEMS / 4);
    cvt_tf32_kernel<<<128, 256>>>(Wk, pwt + 1 * W_ELEMS, W_ELEMS / 4);
    cvt_tf32_kernel<<<128, 256>>>(Wv, pwt + 2 * W_ELEMS, W_ELEMS / 4);
    cvt_tf32_kernel<<<128, 256>>>(Wo, pwt + 3 * W_ELEMS, W_ELEMS / 4);

    cudaFuncSetAttribute((const void*)tf32_gemm_kernel,
                         cudaFuncAttributeMaxDynamicSharedMemorySize, GEMM_SMEM);

    // fused QKV projections: Q fp32, K/V fp16
    dim3 qkv_grid(DD / 128, BT / 128, 3);
    tf32_gemm_kernel<<<qkv_grid, 256, GEMM_SMEM>>>(
        pxt, pwt + 0 * W_ELEMS, pwt + 1 * W_ELEMS, pwt + 2 * W_ELEMS,
        pq, nullptr, nullptr,
        nullptr, pkh, pvh,
        BT, DD, DD);

    cudaFuncSetAttribute((const void*)attn_kernel,
                         cudaFuncAttributeMaxDynamicSharedMemorySize, ATTN_SMEM);
    attn_kernel<<<BB * 32, 512, ATTN_SMEM>>>(pq, pkh, pvh, aq, ak, av, patt);

    dim3 o_grid(DD / 128, BT / 128, 1);
    tf32_gemm_kernel<<<o_grid, 256, GEMM_SMEM>>>(
        patt, pwt + 3 * W_ELEMS, pwt + 3 * W_ELEMS, pwt + 3 * W_ELEMS,
        out, out, out,
        nullptr, nullptr, nullptr,
        BT, DD, DD);
}

// round 11
// speedup vs baseline: 1.8709x; 1.2230x over previous
#include <cuda_runtime.h>
#include <cuda_bf16.h>
#include <cuda_fp16.h>
#include <math.h>

// Problem constants
#define BB 128
#define TT 64
#define DD 1024
#define HH 16
#define HDD 64
#define BT (BB*TT)        // 8192

// Scratch (device globals: allocation-free rule)
__device__ float  g_q[BT*DD];
__device__ __half g_kh[BT*DD];
__device__ __half g_vh[BT*DD];
__device__ __half g_atth[BT*DD];
__device__ __half g_xh[BT*DD];        // fp16 x
__device__ __half g_wth[4*DD*DD];     // fp16 transposed Wq,Wk,Wv,Wo ([n][k])

__device__ __forceinline__ void mma_f16(float c[4], const unsigned a[4], const unsigned b[2]) {
    asm volatile(
        "mma.sync.aligned.m16n8k16.row.col.f32.f16.f16.f32 "
        "{%0,%1,%2,%3}, {%4,%5,%6,%7}, {%8,%9}, {%0,%1,%2,%3};"
        : "+f"(c[0]), "+f"(c[1]), "+f"(c[2]), "+f"(c[3])
        : "r"(a[0]), "r"(a[1]), "r"(a[2]), "r"(a[3]),
          "r"(b[0]), "r"(b[1]));
}

__device__ __forceinline__ void cp_async16(void* smem, const void* gmem) {
    unsigned s = (unsigned)__cvta_generic_to_shared(smem);
    asm volatile("cp.async.cg.shared.global [%0], [%1], 16;\n" :: "r"(s), "l"(gmem));
}
#define CP_COMMIT() asm volatile("cp.async.commit_group;\n" ::: "memory")
#define CP_WAIT0()  asm volatile("cp.async.wait_group 0;\n" ::: "memory")

// ---------------------------------------------------------------------------
// x: fp32 -> fp16
// ---------------------------------------------------------------------------
__global__ __launch_bounds__(256) void cvt_f16_kernel(
    const float* __restrict__ src, __half* __restrict__ dst, int n4)
{
    int i = blockIdx.x * blockDim.x + threadIdx.x;
    int stride = gridDim.x * blockDim.x;
    const float4* s4 = reinterpret_cast<const float4*>(src);
    uint2* d4 = reinterpret_cast<uint2*>(dst);
    for (; i < n4; i += stride) {
        float4 v = s4[i];
        __half2 h01 = __floats2half2_rn(v.x, v.y);
        __half2 h23 = __floats2half2_rn(v.z, v.w);
        uint2 p;
        p.x = *reinterpret_cast<unsigned*>(&h01);
        p.y = *reinterpret_cast<unsigned*>(&h23);
        d4[i] = p;
    }
}

// ---------------------------------------------------------------------------
// Weight transpose + cvt: W[k][n] fp32 -> WT[n][k] fp16. grid.z picks matrix.
// 32x32 tiles, block (32, 8).
// ---------------------------------------------------------------------------
__global__ __launch_bounds__(256) void wt_transpose_kernel(
    const float* __restrict__ W0, const float* __restrict__ W1,
    const float* __restrict__ W2, const float* __restrict__ W3,
    __half* __restrict__ out)   // [4][DD][DD]
{
    __shared__ float tile[32][33];
    const float* W = (blockIdx.z == 0) ? W0 : (blockIdx.z == 1) ? W1 :
                     (blockIdx.z == 2) ? W2 : W3;
    __half* WT = out + (size_t)blockIdx.z * DD * DD;

    int n0 = blockIdx.x * 32;
    int k0 = blockIdx.y * 32;
    int tx = threadIdx.x, ty = threadIdx.y;
#pragma unroll
    for (int j = 0; j < 32; j += 8)
        tile[ty + j][tx] = W[(size_t)(k0 + ty + j) * DD + n0 + tx];
    __syncthreads();
#pragma unroll
    for (int j = 0; j < 32; j += 8)
        WT[(size_t)(n0 + ty + j) * DD + k0 + tx] = __float2half(tile[tx][ty + j]);
}

// ---------------------------------------------------------------------------
// FP16 tensor-core GEMM (m16n8k16, f32 accum), cp.async double buffer.
// C[M,N] = A[M,K] @ B^T  with A fp16 [m][k], WT fp16 [n][k].
// BM=BN=128, BK=32, 256 threads (8 warps 4m x 2n), warp tile 32x64.
// smem halves, stride 40/row. blockIdx.z selects WT/C; H!=null => fp16 out.
// ---------------------------------------------------------------------------
#define HST 40                        // halves per smem row
#define HTILE (128*HST)               // halves per tile (A or B)
#define GEMM_SMEM (2 * 2 * HTILE * 2) // bytes = 40960

__global__ __launch_bounds__(256) void h_gemm_kernel(
    const __half* __restrict__ A,
    const __half* __restrict__ B0, const __half* __restrict__ B1,
    const __half* __restrict__ B2,
    float* __restrict__ C0, float* __restrict__ C1, float* __restrict__ C2,
    __half* __restrict__ H0, __half* __restrict__ H1, __half* __restrict__ H2,
    int M, int N, int K)
{
    extern __shared__ __half hsm[];
    __half* sAb = hsm;                  // [2][128][40]
    __half* sBb = hsm + 2 * HTILE;      // [2][128][40]

    const __half* Bt = (blockIdx.z == 0) ? B0 : (blockIdx.z == 1) ? B1 : B2;
    float*        C  = (blockIdx.z == 0) ? C0 : (blockIdx.z == 1) ? C1 : C2;
    __half*       Hp = (blockIdx.z == 0) ? H0 : (blockIdx.z == 1) ? H1 : H2;

    const int tid  = threadIdx.x;
    const int lane = tid & 31;
    const int wid  = tid >> 5;
    const int wm   = (wid & 3) * 32;
    const int wn   = (wid >> 2) * 64;
    const int g    = lane >> 2;
    const int t    = lane & 3;

    const int m0 = blockIdx.y * 128;
    const int n0 = blockIdx.x * 128;

    float acc[2][8][4];
#pragma unroll
    for (int mt = 0; mt < 2; mt++)
#pragma unroll
        for (int nt = 0; nt < 8; nt++)
#pragma unroll
            for (int i = 0; i < 4; i++) acc[mt][nt][i] = 0.f;

    // stage: A rows m0..m0+127, k0..k0+31 (64B per row = 4 chunks of 16B)
    auto load_stage = [&](int st, int k0) {
        __half* sA = sAb + st * HTILE;
        __half* sB = sBb + st * HTILE;
#pragma unroll
        for (int r = 0; r < 2; r++) {
            int f   = tid + r * 256;        // 0..511
            int row = f >> 2;               // 0..127
            int ch  = f & 3;                // 16B chunk = 8 halves
            cp_async16(&sA[row * HST + ch * 8],
                       &A[(size_t)(m0 + row) * K + k0 + ch * 8]);
        }
#pragma unroll
        for (int r = 0; r < 2; r++) {
            int f   = tid + r * 256;
            int row = f >> 2;
            int ch  = f & 3;
            cp_async16(&sB[row * HST + ch * 8],
                       &Bt[(size_t)(n0 + row) * K + k0 + ch * 8]);
        }
    };

    load_stage(0, 0);
    CP_COMMIT();
    CP_WAIT0();
    __syncthreads();

    int st = 0;
    for (int k0 = 0; k0 < K; k0 += 32) {
        const int nxt = k0 + 32;
        if (nxt < K) {
            load_stage(st ^ 1, nxt);
            CP_COMMIT();
        }

        const __half2* A2 = reinterpret_cast<const __half2*>(sAb + st * HTILE);
        const __half2* B2h = reinterpret_cast<const __half2*>(sBb + st * HTILE);
        const int H2ST = HST / 2;   // 20 half2 per row

#pragma unroll
        for (int ks = 0; ks < 2; ks++) {
            const int kb = ks * 8;          // half2 offset of this k16 step
            unsigned af[2][4];
#pragma unroll
            for (int mt = 0; mt < 2; mt++) {
                const int row = wm + mt * 16;
                af[mt][0] = *reinterpret_cast<const unsigned*>(&A2[(row + g    ) * H2ST + kb + t    ]);
                af[mt][1] = *reinterpret_cast<const unsigned*>(&A2[(row + g + 8) * H2ST + kb + t    ]);
                af[mt][2] = *reinterpret_cast<const unsigned*>(&A2[(row + g    ) * H2ST + kb + t + 4]);
                af[mt][3] = *reinterpret_cast<const unsigned*>(&A2[(row + g + 8) * H2ST + kb + t + 4]);
            }
            unsigned bf[8][2];
#pragma unroll
            for (int nt = 0; nt < 8; nt++) {
                const int col = wn + nt * 8 + g;
                bf[nt][0] = *reinterpret_cast<const unsigned*>(&B2h[col * H2ST + kb + t    ]);
                bf[nt][1] = *reinterpret_cast<const unsigned*>(&B2h[col * H2ST + kb + t + 4]);
            }
#pragma unroll
            for (int mt = 0; mt < 2; mt++)
#pragma unroll
                for (int nt = 0; nt < 8; nt++)
                    mma_f16(acc[mt][nt], af[mt], bf[nt]);
        }

        if (nxt < K) CP_WAIT0();
        __syncthreads();
        st ^= 1;
    }

#pragma unroll
    for (int mt = 0; mt < 2; mt++) {
#pragma unroll
        for (int nt = 0; nt < 8; nt++) {
            const size_t row = (size_t)(m0 + wm + mt * 16 + g);
            const int    col = n0 + wn + nt * 8 + 2 * t;
            if (Hp) {
                __half2 lo = __floats2half2_rn(acc[mt][nt][0], acc[mt][nt][1]);
                __half2 hi = __floats2half2_rn(acc[mt][nt][2], acc[mt][nt][3]);
                *reinterpret_cast<__half2*>(&Hp[row * N + col])       = lo;
                *reinterpret_cast<__half2*>(&Hp[(row + 8) * N + col]) = hi;
            } else {
                float2 lo = make_float2(acc[mt][nt][0], acc[mt][nt][1]);
                float2 hi = make_float2(acc[mt][nt][2], acc[mt][nt][3]);
                *reinterpret_cast<float2*>(&C[row * N + col])       = lo;
                *reinterpret_cast<float2*>(&C[(row + 8) * N + col]) = hi;
            }
        }
    }
}

// ---------------------------------------------------------------------------
// Fused smolgen attention (R9 structure): block per (b, q-pair), 512 thr,
// 2 blk/SM. fp16 K/V + a_k/a_v, half2 loops, rotation swizzle.
// att output written fp16 (feeds Wo GEMM).
// ---------------------------------------------------------------------------
#define SWZ2(k, d2) (((d2) + 4*(k)) & 31)

#define SQ_OFF    0                       // float[2][1024]
#define SKV_OFF   2048                    // half[2buf][2][4096] = 8192 floats
#define SAK_OFF   (2048 + 8192)           // half[2][4096] = 4096 floats
#define SAV_OFF   (SAK_OFF + 4096)
#define SLOG_OFF  (SAV_OFF + 4096)        // float[2][64]
#define SRED_OFF  (SLOG_OFF + 128)        // float[1024]
#define ATTN_SMEM ((SRED_OFF + 1024) * 4)

__global__ __launch_bounds__(512, 2) void attn_kernel(
    const float* __restrict__ Q, const __half* __restrict__ Kt,
    const __half* __restrict__ V,
    const float* __restrict__ AQ, const float* __restrict__ AK,
    const float* __restrict__ AV, __half* __restrict__ Out)
{
    extern __shared__ float smem[];
    float*   sQ   = smem + SQ_OFF;
    __half2* sKV  = reinterpret_cast<__half2*>(smem + SKV_OFF);
    __half2* sAk  = reinterpret_cast<__half2*>(smem + SAK_OFF);
    __half2* sAv  = reinterpret_cast<__half2*>(smem + SAV_OFF);
    float*   sLog = smem + SLOG_OFF;
    float*   sRed = smem + SRED_OFF;

    const int t    = threadIdx.x;
    const int lane = t & 31;
    const int b    = blockIdx.x >> 5;
    const int qg   = blockIdx.x & 31;
    const int row0 = b * TT + qg * 2;

    const int qp   = t >> 8;
    const int loc  = t & 255;
    const int lk   = loc >> 2;
    const int lp   = loc & 3;
    const int od2  = loc & 31;
    const int okp  = loc >> 5;

    reinterpret_cast<float4*>(sQ)[t] =
        reinterpret_cast<const float4*>(Q + (size_t)row0 * DD)[t];

#pragma unroll
    for (int r = 0; r < 8; r++) {
        int c   = t + r * 512;
        int ten = c >> 11;
        int rem = c & 2047;
        int qq  = rem >> 10;
        int rm2 = rem & 1023;
        int kk  = rm2 >> 4;
        int j   = rm2 & 15;
        const float* src = (ten ? AV : AK) +
            (((size_t)(row0 + qq)) * TT + kk) * HDD + 4 * j;
        float4 v = *reinterpret_cast<const float4*>(src);
        uint2 packed;
        {
            __half2 h01 = __floats2half2_rn(v.x, v.y);
            __half2 h23 = __floats2half2_rn(v.z, v.w);
            packed.x = *reinterpret_cast<unsigned*>(&h01);
            packed.y = *reinterpret_cast<unsigned*>(&h23);
        }
        __half2* dst = (ten ? sAv : sAk) + qq * 2048 + kk * 32 + SWZ2(kk, 2 * j);
        *reinterpret_cast<uint2*>(dst) = packed;
    }

    float2 aq_r[8];
    {
        const float* aqp = AQ + (((size_t)(row0 + qp)) * TT + lk) * HDD + 2 * lp;
#pragma unroll
        for (int i = 0; i < 8; i++)
            aq_r[i] = *reinterpret_cast<const float2*>(aqp + 8 * i);
    }

    const __half* khB = Kt + (size_t)b * TT * DD;
    const __half* vhB = V  + (size_t)b * TT * DD;

    auto stage_kv = [&](int buf, int h) {
        const int hoff = h * HDD;
#pragma unroll
        for (int r = 0; r < 2; r++) {
            int c   = t + r * 512;
            int ten = c >> 9;
            int rem = c & 511;
            int kk  = rem >> 3;
            int j   = rem & 7;
            const __half* src = (ten ? vhB : khB) + (size_t)kk * DD + hoff + 8 * j;
            __half2* dst = sKV + buf * 4096 + ten * 2048 + kk * 32 + SWZ2(kk, 4 * j);
            cp_async16(dst, src);
        }
    };

    stage_kv(0, 0);
    CP_COMMIT();
    CP_WAIT0();
    __syncthreads();

    int cur = 0;
    for (int h = 0; h < HH; h++) {
        const int hoff = h * HDD;

        if (h + 1 < HH) {
            stage_kv(cur ^ 1, h + 1);
            CP_COMMIT();
        }

        // logits
        {
            const float2*  qh = reinterpret_cast<const float2*>(sQ + qp * DD + hoff);
            const __half2* kp = sKV + cur * 4096;
            const __half2* ap = sAk + qp * 2048;
            float c = 0.f, bq = 0.f, bk = 0.f;
#pragma unroll
            for (int i = 0; i < 8; i++) {
                int d2 = lp + 4 * i;
                int so = lk * 32 + SWZ2(lk, d2);
                float2 kv  = __half22float2(kp[so]);
                float2 ak2 = __half22float2(ap[so]);
                float2 qv  = qh[d2];
                c  += qv.x * kv.x + qv.y * kv.y;
                bq += aq_r[i].x * kv.x + aq_r[i].y * kv.y;
                bk += qv.x * ak2.x + qv.y * ak2.y;
            }
            float l = c * 0.125f + bq + bk;
            l += __shfl_xor_sync(0xffffffffu, l, 1);
            l += __shfl_xor_sync(0xffffffffu, l, 2);
            if (lp == 0) sLog[qp * 64 + lk] = l;
        }
        __syncthreads();

        // per-warp softmax
        float p0, p1;
        {
            float a  = sLog[qp * 64 + lane];
            float b2 = sLog[qp * 64 + lane + 32];
            float m = fmaxf(a, b2);
#pragma unroll
            for (int o = 16; o; o >>= 1)
                m = fmaxf(m, __shfl_xor_sync(0xffffffffu, m, o));
            float ea = __expf(a - m), eb = __expf(b2 - m);
            float s = ea + eb;
#pragma unroll
            for (int o = 16; o; o >>= 1)
                s += __shfl_xor_sync(0xffffffffu, s, o);
            float inv = 1.0f / s;
            p0 = ea * inv;
            p1 = eb * inv;
        }

        // output partials
        {
            const __half2* vp = sKV + cur * 4096 + 2048;
            const __half2* ap = sAv + qp * 2048;
            float2 acc = make_float2(0.f, 0.f);
#pragma unroll
            for (int i = 0; i < 8; i++) {
                int k  = okp * 8 + i;
                float pk = __shfl_sync(0xffffffffu, (okp < 4) ? p0 : p1, k & 31);
                int so = k * 32 + SWZ2(k, od2);
                float2 vv  = __half22float2(vp[so]);
                float2 av2 = __half22float2(ap[so]);
                acc.x += pk * (vv.x + av2.x);
                acc.y += pk * (vv.y + av2.y);
            }
            reinterpret_cast<float2*>(sRed)[(qp * 8 + okp) * 32 + od2] = acc;
        }
        __syncthreads();

        if (t < 128) {
            int qq = t >> 6;
            int dd = t & 63;
            const float* rp = sRed + qq * 512 + dd;
            float o = rp[0] + rp[64] + rp[128] + rp[192]
                    + rp[256] + rp[320] + rp[384] + rp[448];
            Out[(size_t)(row0 + qq) * DD + hoff + dd] = __float2half(o);
        }

        CP_WAIT0();
        __syncthreads();
        cur ^= 1;
    }
}

// ---------------------------------------------------------------------------
extern "C" void kernel_launch(void* const* d_in, const int* in_sizes, int n_in,
                              void* d_out, int out_size)
{
    const float* x  = (const float*)d_in[0];
    const float* aq = (const float*)d_in[1];
    const float* ak = (const float*)d_in[2];
    const float* av = (const float*)d_in[3];
    const float* Wq = (const float*)d_in[4];
    const float* Wk = (const float*)d_in[5];
    const float* Wv = (const float*)d_in[6];
    const float* Wo = (const float*)d_in[7];
    float* out = (float*)d_out;

    float *pq;
    __half *pkh, *pvh, *patth, *pxh, *pwth;
    cudaGetSymbolAddress((void**)&pq,    g_q);
    cudaGetSymbolAddress((void**)&pkh,   g_kh);
    cudaGetSymbolAddress((void**)&pvh,   g_vh);
    cudaGetSymbolAddress((void**)&patth, g_atth);
    cudaGetSymbolAddress((void**)&pxh,   g_xh);
    cudaGetSymbolAddress((void**)&pwth,  g_wth);

    const int W_ELEMS = DD * DD;

    // x -> fp16
    cvt_f16_kernel<<<512, 256>>>(x, pxh, BT * DD / 4);
    // weights -> transposed fp16 (grid.z picks matrix)
    {
        dim3 tgrid(DD / 32, DD / 32, 4);
        dim3 tblk(32, 8);
        wt_transpose_kernel<<<tgrid, tblk>>>(Wq, Wk, Wv, Wo, pwth);
    }

    cudaFuncSetAttribute((const void*)h_gemm_kernel,
                         cudaFuncAttributeMaxDynamicSharedMemorySize, GEMM_SMEM);

    // fused QKV projections: Q fp32, K/V fp16
    dim3 qkv_grid(DD / 128, BT / 128, 3);
    h_gemm_kernel<<<qkv_grid, 256, GEMM_SMEM>>>(
        pxh,
        pwth + 0 * W_ELEMS, pwth + 1 * W_ELEMS, pwth + 2 * W_ELEMS,
        pq, nullptr, nullptr,
        nullptr, pkh, pvh,
        BT, DD, DD);

    cudaFuncSetAttribute((const void*)attn_kernel,
                         cudaFuncAttributeMaxDynamicSharedMemorySize, ATTN_SMEM);
    attn_kernel<<<BB * 32, 512, ATTN_SMEM>>>(pq, pkh, pvh, aq, ak, av, patth);

    // Wo GEMM: att fp16 @ Wo^T -> out fp32
    dim3 o_grid(DD / 128, BT / 128, 1);
    h_gemm_kernel<<<o_grid, 256, GEMM_SMEM>>>(
        patth,
        pwth + 3 * W_ELEMS, pwth + 3 * W_ELEMS, pwth + 3 * W_ELEMS,
        out, out, out,
        nullptr, nullptr, nullptr,
        BT, DD, DD);
}

// round 12
// speedup vs baseline: 1.9421x; 1.0381x over previous
#include <cuda_runtime.h>
#include <cuda_bf16.h>
#include <cuda_fp16.h>
#include <math.h>

// Problem constants
#define BB 128
#define TT 64
#define DD 1024
#define HH 16
#define HDD 64
#define BT (BB*TT)        // 8192

// Scratch (device globals: allocation-free rule)
__device__ float  g_q[BT*DD];
__device__ __half g_kh[BT*DD];
__device__ __half g_vh[BT*DD];
__device__ __half g_atth[BT*DD];
__device__ __half g_xh[BT*DD];        // fp16 x
__device__ __half g_wth[4*DD*DD];     // fp16 transposed Wq,Wk,Wv,Wo ([n][k])

__device__ __forceinline__ void mma_f16(float c[4], const unsigned a[4], const unsigned b[2]) {
    asm volatile(
        "mma.sync.aligned.m16n8k16.row.col.f32.f16.f16.f32 "
        "{%0,%1,%2,%3}, {%4,%5,%6,%7}, {%8,%9}, {%0,%1,%2,%3};"
        : "+f"(c[0]), "+f"(c[1]), "+f"(c[2]), "+f"(c[3])
        : "r"(a[0]), "r"(a[1]), "r"(a[2]), "r"(a[3]),
          "r"(b[0]), "r"(b[1]));
}

// Packed f32x2 FMA (Blackwell): c += a * b, 2 lanes per issue.
__device__ __forceinline__ void ffma2(float2& c, float2 a, float2 b) {
    asm("{\n\t"
        ".reg .b64 ra, rb, rc;\n\t"
        "mov.b64 ra, {%2, %3};\n\t"
        "mov.b64 rb, {%4, %5};\n\t"
        "mov.b64 rc, {%0, %1};\n\t"
        "fma.rn.f32x2 rc, ra, rb, rc;\n\t"
        "mov.b64 {%0, %1}, rc;\n\t"
        "}"
        : "+f"(c.x), "+f"(c.y)
        : "f"(a.x), "f"(a.y), "f"(b.x), "f"(b.y));
}

__device__ __forceinline__ void cp_async16(void* smem, const void* gmem) {
    unsigned s = (unsigned)__cvta_generic_to_shared(smem);
    asm volatile("cp.async.cg.shared.global [%0], [%1], 16;\n" :: "r"(s), "l"(gmem));
}
#define CP_COMMIT() asm volatile("cp.async.commit_group;\n" ::: "memory")
#define CP_WAIT0()  asm volatile("cp.async.wait_group 0;\n" ::: "memory")

// ---------------------------------------------------------------------------
// x: fp32 -> fp16
// ---------------------------------------------------------------------------
__global__ __launch_bounds__(256) void cvt_f16_kernel(
    const float* __restrict__ src, __half* __restrict__ dst, int n4)
{
    int i = blockIdx.x * blockDim.x + threadIdx.x;
    int stride = gridDim.x * blockDim.x;
    const float4* s4 = reinterpret_cast<const float4*>(src);
    uint2* d4 = reinterpret_cast<uint2*>(dst);
    for (; i < n4; i += stride) {
        float4 v = s4[i];
        __half2 h01 = __floats2half2_rn(v.x, v.y);
        __half2 h23 = __floats2half2_rn(v.z, v.w);
        uint2 p;
        p.x = *reinterpret_cast<unsigned*>(&h01);
        p.y = *reinterpret_cast<unsigned*>(&h23);
        d4[i] = p;
    }
}

// ---------------------------------------------------------------------------
// Weight transpose + cvt: W[k][n] fp32 -> WT[n][k] fp16. grid.z picks matrix.
// ---------------------------------------------------------------------------
__global__ __launch_bounds__(256) void wt_transpose_kernel(
    const float* __restrict__ W0, const float* __restrict__ W1,
    const float* __restrict__ W2, const float* __restrict__ W3,
    __half* __restrict__ out)   // [4][DD][DD]
{
    __shared__ float tile[32][33];
    const float* W = (blockIdx.z == 0) ? W0 : (blockIdx.z == 1) ? W1 :
                     (blockIdx.z == 2) ? W2 : W3;
    __half* WT = out + (size_t)blockIdx.z * DD * DD;

    int n0 = blockIdx.x * 32;
    int k0 = blockIdx.y * 32;
    int tx = threadIdx.x, ty = threadIdx.y;
#pragma unroll
    for (int j = 0; j < 32; j += 8)
        tile[ty + j][tx] = W[(size_t)(k0 + ty + j) * DD + n0 + tx];
    __syncthreads();
#pragma unroll
    for (int j = 0; j < 32; j += 8)
        WT[(size_t)(n0 + ty + j) * DD + k0 + tx] = __float2half(tile[tx][ty + j]);
}

// ---------------------------------------------------------------------------
// FP16 tensor-core GEMM (m16n8k16, f32 accum), cp.async double buffer.
// (unchanged from R11)
// ---------------------------------------------------------------------------
#define HST 40
#define HTILE (128*HST)
#define GEMM_SMEM (2 * 2 * HTILE * 2)

__global__ __launch_bounds__(256) void h_gemm_kernel(
    const __half* __restrict__ A,
    const __half* __restrict__ B0, const __half* __restrict__ B1,
    const __half* __restrict__ B2,
    float* __restrict__ C0, float* __restrict__ C1, float* __restrict__ C2,
    __half* __restrict__ H0, __half* __restrict__ H1, __half* __restrict__ H2,
    int M, int N, int K)
{
    extern __shared__ __half hsm[];
    __half* sAb = hsm;
    __half* sBb = hsm + 2 * HTILE;

    const __half* Bt = (blockIdx.z == 0) ? B0 : (blockIdx.z == 1) ? B1 : B2;
    float*        C  = (blockIdx.z == 0) ? C0 : (blockIdx.z == 1) ? C1 : C2;
    __half*       Hp = (blockIdx.z == 0) ? H0 : (blockIdx.z == 1) ? H1 : H2;

    const int tid  = threadIdx.x;
    const int lane = tid & 31;
    const int wid  = tid >> 5;
    const int wm   = (wid & 3) * 32;
    const int wn   = (wid >> 2) * 64;
    const int g    = lane >> 2;
    const int t    = lane & 3;

    const int m0 = blockIdx.y * 128;
    const int n0 = blockIdx.x * 128;

    float acc[2][8][4];
#pragma unroll
    for (int mt = 0; mt < 2; mt++)
#pragma unroll
        for (int nt = 0; nt < 8; nt++)
#pragma unroll
            for (int i = 0; i < 4; i++) acc[mt][nt][i] = 0.f;

    auto load_stage = [&](int st, int k0) {
        __half* sA = sAb + st * HTILE;
        __half* sB = sBb + st * HTILE;
#pragma unroll
        for (int r = 0; r < 2; r++) {
            int f   = tid + r * 256;
            int row = f >> 2;
            int ch  = f & 3;
            cp_async16(&sA[row * HST + ch * 8],
                       &A[(size_t)(m0 + row) * K + k0 + ch * 8]);
        }
#pragma unroll
        for (int r = 0; r < 2; r++) {
            int f   = tid + r * 256;
            int row = f >> 2;
            int ch  = f & 3;
            cp_async16(&sB[row * HST + ch * 8],
                       &Bt[(size_t)(n0 + row) * K + k0 + ch * 8]);
        }
    };

    load_stage(0, 0);
    CP_COMMIT();
    CP_WAIT0();
    __syncthreads();

    int st = 0;
    for (int k0 = 0; k0 < K; k0 += 32) {
        const int nxt = k0 + 32;
        if (nxt < K) {
            load_stage(st ^ 1, nxt);
            CP_COMMIT();
        }

        const __half2* A2 = reinterpret_cast<const __half2*>(sAb + st * HTILE);
        const __half2* B2h = reinterpret_cast<const __half2*>(sBb + st * HTILE);
        const int H2ST = HST / 2;

#pragma unroll
        for (int ks = 0; ks < 2; ks++) {
            const int kb = ks * 8;
            unsigned af[2][4];
#pragma unroll
            for (int mt = 0; mt < 2; mt++) {
                const int row = wm + mt * 16;
                af[mt][0] = *reinterpret_cast<const unsigned*>(&A2[(row + g    ) * H2ST + kb + t    ]);
                af[mt][1] = *reinterpret_cast<const unsigned*>(&A2[(row + g + 8) * H2ST + kb + t    ]);
                af[mt][2] = *reinterpret_cast<const unsigned*>(&A2[(row + g    ) * H2ST + kb + t + 4]);
                af[mt][3] = *reinterpret_cast<const unsigned*>(&A2[(row + g + 8) * H2ST + kb + t + 4]);
            }
            unsigned bf[8][2];
#pragma unroll
            for (int nt = 0; nt < 8; nt++) {
                const int col = wn + nt * 8 + g;
                bf[nt][0] = *reinterpret_cast<const unsigned*>(&B2h[col * H2ST + kb + t    ]);
                bf[nt][1] = *reinterpret_cast<const unsigned*>(&B2h[col * H2ST + kb + t + 4]);
            }
#pragma unroll
            for (int mt = 0; mt < 2; mt++)
#pragma unroll
                for (int nt = 0; nt < 8; nt++)
                    mma_f16(acc[mt][nt], af[mt], bf[nt]);
        }

        if (nxt < K) CP_WAIT0();
        __syncthreads();
        st ^= 1;
    }

#pragma unroll
    for (int mt = 0; mt < 2; mt++) {
#pragma unroll
        for (int nt = 0; nt < 8; nt++) {
            const size_t row = (size_t)(m0 + wm + mt * 16 + g);
            const int    col = n0 + wn + nt * 8 + 2 * t;
            if (Hp) {
                __half2 lo = __floats2half2_rn(acc[mt][nt][0], acc[mt][nt][1]);
                __half2 hi = __floats2half2_rn(acc[mt][nt][2], acc[mt][nt][3]);
                *reinterpret_cast<__half2*>(&Hp[row * N + col])       = lo;
                *reinterpret_cast<__half2*>(&Hp[(row + 8) * N + col]) = hi;
            } else {
                float2 lo = make_float2(acc[mt][nt][0], acc[mt][nt][1]);
                float2 hi = make_float2(acc[mt][nt][2], acc[mt][nt][3]);
                *reinterpret_cast<float2*>(&C[row * N + col])       = lo;
                *reinterpret_cast<float2*>(&C[(row + 8) * N + col]) = hi;
            }
        }
    }
}

// ---------------------------------------------------------------------------
// Fused smolgen attention v12: block per (b, q-pair), 512 thr, 2 blk/SM.
// Padded stride 36 half2 per row (no swizzle):
//   logits banks: (4*lk + lp + 4i) % 32 bijective per warp, all i
//   output banks: (od2 + 4i) % 32 bijective per warp, all i
// => conflict-free AND affine inner-loop addresses (imm-offset LDS).
// Logits accumulated with packed fma.rn.f32x2.
// ---------------------------------------------------------------------------
#define H2ROW 36                          // half2 per row (72 halves)
#define H2TILE (TT*H2ROW)                 // 2304 half2 per 64x64 tile

#define SQ_OFF    0                                  // float[2][1024]
#define SKV_OFF   2048                               // half2[2buf][2][2304] -> 4608 floats
#define SAK_OFF   (SKV_OFF + 2*2*H2TILE/1*1 + 0)     // placeholder (computed below)
// float offsets (1 float = 1 half2):
//   SKV: 2*2*2304 = 9216 floats
//   SAK: 2*2304   = 4608 floats
//   SAV: 2*2304   = 4608 floats
#define SKV_FLOATS (2*2*H2TILE)
#define SAK_OFF2  (SKV_OFF + SKV_FLOATS)
#define SAV_OFF2  (SAK_OFF2 + 2*H2TILE)
#define SLOG_OFF  (SAV_OFF2 + 2*H2TILE)              // float[2][64]
#define SRED_OFF  (SLOG_OFF + 128)                   // float[1024]
#define ATTN_SMEM ((SRED_OFF + 1024) * 4)            // 86528 bytes

__global__ __launch_bounds__(512, 2) void attn_kernel(
    const float* __restrict__ Q, const __half* __restrict__ Kt,
    const __half* __restrict__ V,
    const float* __restrict__ AQ, const float* __restrict__ AK,
    const float* __restrict__ AV, __half* __restrict__ Out)
{
    extern __shared__ float smem[];
    float*   sQ   = smem + SQ_OFF;
    __half2* sKV  = reinterpret_cast<__half2*>(smem + SKV_OFF);   // [2buf][2][64][36]
    __half2* sAk  = reinterpret_cast<__half2*>(smem + SAK_OFF2);  // [2q][64][36]
    __half2* sAv  = reinterpret_cast<__half2*>(smem + SAV_OFF2);
    float*   sLog = smem + SLOG_OFF;
    float*   sRed = smem + SRED_OFF;

    const int t    = threadIdx.x;
    const int lane = t & 31;
    const int b    = blockIdx.x >> 5;
    const int qg   = blockIdx.x & 31;
    const int row0 = b * TT + qg * 2;

    const int qp   = t >> 8;
    const int loc  = t & 255;
    const int lk   = loc >> 2;
    const int lp   = loc & 3;
    const int od2  = loc & 31;
    const int okp  = loc >> 5;

    // ---- prologue ----
    reinterpret_cast<float4*>(sQ)[t] =
        reinterpret_cast<const float4*>(Q + (size_t)row0 * DD)[t];

    // a_k / a_v: fp32 gmem -> fp16 padded smem
#pragma unroll
    for (int r = 0; r < 8; r++) {
        int c   = t + r * 512;
        int ten = c >> 11;
        int rem = c & 2047;
        int qq  = rem >> 10;
        int rm2 = rem & 1023;
        int kk  = rm2 >> 4;
        int j   = rm2 & 15;                // float4 id -> d2 base 2j
        const float* src = (ten ? AV : AK) +
            (((size_t)(row0 + qq)) * TT + kk) * HDD + 4 * j;
        float4 v = *reinterpret_cast<const float4*>(src);
        uint2 packed;
        {
            __half2 h01 = __floats2half2_rn(v.x, v.y);
            __half2 h23 = __floats2half2_rn(v.z, v.w);
            packed.x = *reinterpret_cast<unsigned*>(&h01);
            packed.y = *reinterpret_cast<unsigned*>(&h23);
        }
        __half2* dst = (ten ? sAv : sAk) + qq * H2TILE + kk * H2ROW + 2 * j;
        *reinterpret_cast<uint2*>(dst) = packed;
    }

    float2 aq_r[8];
    {
        const float* aqp = AQ + (((size_t)(row0 + qp)) * TT + lk) * HDD + 2 * lp;
#pragma unroll
        for (int i = 0; i < 8; i++)
            aq_r[i] = *reinterpret_cast<const float2*>(aqp + 8 * i);
    }

    const __half* khB = Kt + (size_t)b * TT * DD;
    const __half* vhB = V  + (size_t)b * TT * DD;

    auto stage_kv = [&](int buf, int h) {
        const int hoff = h * HDD;
#pragma unroll
        for (int r = 0; r < 2; r++) {
            int c   = t + r * 512;
            int ten = c >> 9;
            int rem = c & 511;
            int kk  = rem >> 3;
            int j   = rem & 7;             // 16B chunk -> d2 base 4j
            const __half* src = (ten ? vhB : khB) + (size_t)kk * DD + hoff + 8 * j;
            __half2* dst = sKV + buf * 2 * H2TILE + ten * H2TILE + kk * H2ROW + 4 * j;
            cp_async16(dst, src);
        }
    };

    stage_kv(0, 0);
    CP_COMMIT();
    CP_WAIT0();
    __syncthreads();

    int cur = 0;
    for (int h = 0; h < HH; h++) {
        const int hoff = h * HDD;

        if (h + 1 < HH) {
            stage_kv(cur ^ 1, h + 1);
            CP_COMMIT();
        }

        // ---- logits (f32x2 packed fma; affine smem addressing) ----
        {
            const float2*  qh = reinterpret_cast<const float2*>(sQ + qp * DD + hoff);
            const __half2* kp = sKV + cur * 2 * H2TILE + lk * H2ROW + lp;
            const __half2* ap = sAk + qp * H2TILE + lk * H2ROW + lp;
            float2 c  = make_float2(0.f, 0.f);
            float2 bq = make_float2(0.f, 0.f);
            float2 bk = make_float2(0.f, 0.f);
#pragma unroll
            for (int i = 0; i < 8; i++) {
                float2 kv  = __half22float2(kp[4 * i]);
                float2 ak2 = __half22float2(ap[4 * i]);
                float2 qv  = qh[lp + 4 * i];
                ffma2(c,  qv,      kv);
                ffma2(bq, aq_r[i], kv);
                ffma2(bk, qv,      ak2);
            }
            float l = (c.x + c.y) * 0.125f + (bq.x + bq.y) + (bk.x + bk.y);
            l += __shfl_xor_sync(0xffffffffu, l, 1);
            l += __shfl_xor_sync(0xffffffffu, l, 2);
            if (lp == 0) sLog[qp * 64 + lk] = l;
        }
        __syncthreads();

        // ---- per-warp redundant softmax ----
        float p0, p1;
        {
            float a  = sLog[qp * 64 + lane];
            float b2 = sLog[qp * 64 + lane + 32];
            float m = fmaxf(a, b2);
#pragma unroll
            for (int o = 16; o; o >>= 1)
                m = fmaxf(m, __shfl_xor_sync(0xffffffffu, m, o));
            float ea = __expf(a - m), eb = __expf(b2 - m);
            float s = ea + eb;
#pragma unroll
            for (int o = 16; o; o >>= 1)
                s += __shfl_xor_sync(0xffffffffu, s, o);
            float inv = 1.0f / s;
            p0 = ea * inv;
            p1 = eb * inv;
        }

        // ---- output partials (affine addressing) ----
        {
            const __half2* vp = sKV + cur * 2 * H2TILE + H2TILE + okp * 8 * H2ROW + od2;
            const __half2* ap = sAv + qp * H2TILE + okp * 8 * H2ROW + od2;
            float2 acc = make_float2(0.f, 0.f);
#pragma unroll
            for (int i = 0; i < 8; i++) {
                int k  = okp * 8 + i;
                float pk = __shfl_sync(0xffffffffu, (okp < 4) ? p0 : p1, k & 31);
                float2 vv  = __half22float2(vp[i * H2ROW]);
                float2 av2 = __half22float2(ap[i * H2ROW]);
                acc.x += pk * (vv.x + av2.x);
                acc.y += pk * (vv.y + av2.y);
            }
            reinterpret_cast<float2*>(sRed)[(qp * 8 + okp) * 32 + od2] = acc;
        }
        __syncthreads();

        if (t < 128) {
            int qq = t >> 6;
            int dd = t & 63;
            const float* rp = sRed + qq * 512 + dd;
            float o = rp[0] + rp[64] + rp[128] + rp[192]
                    + rp[256] + rp[320] + rp[384] + rp[448];
            Out[(size_t)(row0 + qq) * DD + hoff + dd] = __float2half(o);
        }

        CP_WAIT0();
        __syncthreads();
        cur ^= 1;
    }
}

// ---------------------------------------------------------------------------
extern "C" void kernel_launch(void* const* d_in, const int* in_sizes, int n_in,
                              void* d_out, int out_size)
{
    const float* x  = (const float*)d_in[0];
    const float* aq = (const float*)d_in[1];
    const float* ak = (const float*)d_in[2];
    const float* av = (const float*)d_in[3];
    const float* Wq = (const float*)d_in[4];
    const float* Wk = (const float*)d_in[5];
    const float* Wv = (const float*)d_in[6];
    const float* Wo = (const float*)d_in[7];
    float* out = (float*)d_out;

    float *pq;
    __half *pkh, *pvh, *patth, *pxh, *pwth;
    cudaGetSymbolAddress((void**)&pq,    g_q);
    cudaGetSymbolAddress((void**)&pkh,   g_kh);
    cudaGetSymbolAddress((void**)&pvh,   g_vh);
    cudaGetSymbolAddress((void**)&patth, g_atth);
    cudaGetSymbolAddress((void**)&pxh,   g_xh);
    cudaGetSymbolAddress((void**)&pwth,  g_wth);

    const int W_ELEMS = DD * DD;

    cvt_f16_kernel<<<512, 256>>>(x, pxh, BT * DD / 4);
    {
        dim3 tgrid(DD / 32, DD / 32, 4);
        dim3 tblk(32, 8);
        wt_transpose_kernel<<<tgrid, tblk>>>(Wq, Wk, Wv, Wo, pwth);
    }

    cudaFuncSetAttribute((const void*)h_gemm_kernel,
                         cudaFuncAttributeMaxDynamicSharedMemorySize, GEMM_SMEM);

    dim3 qkv_grid(DD / 128, BT / 128, 3);
    h_gemm_kernel<<<qkv_grid, 256, GEMM_SMEM>>>(
        pxh,
        pwth + 0 * W_ELEMS, pwth + 1 * W_ELEMS, pwth + 2 * W_ELEMS,
        pq, nullptr, nullptr,
        nullptr, pkh, pvh,
        BT, DD, DD);

    cudaFuncSetAttribute((const void*)attn_kernel,
                         cudaFuncAttributeMaxDynamicSharedMemorySize, ATTN_SMEM);
    attn_kernel<<<BB * 32, 512, ATTN_SMEM>>>(pq, pkh, pvh, aq, ak, av, patth);

    dim3 o_grid(DD / 128, BT / 128, 1);
    h_gemm_kernel<<<o_grid, 256, GEMM_SMEM>>>(
        patth,
        pwth + 3 * W_ELEMS, pwth + 3 * W_ELEMS, pwth + 3 * W_ELEMS,
        out, out, out,
        nullptr, nullptr, nullptr,
        BT, DD, DD);
}

// round 13
// speedup vs baseline: 2.0003x; 1.0300x over previous
#include <cuda_runtime.h>
#include <cuda_bf16.h>
#include <cuda_fp16.h>
#include <math.h>

// Problem constants
#define BB 128
#define TT 64
#define DD 1024
#define HH 16
#define HDD 64
#define BT (BB*TT)        // 8192

// Scratch (device globals: allocation-free rule)
__device__ __half g_qh[BT*DD];
__device__ __half g_kh[BT*DD];
__device__ __half g_vh[BT*DD];
__device__ __half g_atth[BT*DD];
__device__ __half g_xh[BT*DD];        // fp16 x
__device__ __half g_wth[4*DD*DD];     // fp16 transposed Wq,Wk,Wv,Wo ([n][k])

__device__ __forceinline__ void mma_f16(float c[4], const unsigned a[4], const unsigned b[2]) {
    asm volatile(
        "mma.sync.aligned.m16n8k16.row.col.f32.f16.f16.f32 "
        "{%0,%1,%2,%3}, {%4,%5,%6,%7}, {%8,%9}, {%0,%1,%2,%3};"
        : "+f"(c[0]), "+f"(c[1]), "+f"(c[2]), "+f"(c[3])
        : "r"(a[0]), "r"(a[1]), "r"(a[2]), "r"(a[3]),
          "r"(b[0]), "r"(b[1]));
}

// Packed f32x2 FMA (Blackwell): c += a * b
__device__ __forceinline__ void ffma2(float2& c, float2 a, float2 b) {
    asm("{\n\t"
        ".reg .b64 ra, rb, rc;\n\t"
        "mov.b64 ra, {%2, %3};\n\t"
        "mov.b64 rb, {%4, %5};\n\t"
        "mov.b64 rc, {%0, %1};\n\t"
        "fma.rn.f32x2 rc, ra, rb, rc;\n\t"
        "mov.b64 {%0, %1}, rc;\n\t"
        "}"
        : "+f"(c.x), "+f"(c.y)
        : "f"(a.x), "f"(a.y), "f"(b.x), "f"(b.y));
}

__device__ __forceinline__ void cp_async16(void* smem, const void* gmem) {
    unsigned s = (unsigned)__cvta_generic_to_shared(smem);
    asm volatile("cp.async.cg.shared.global [%0], [%1], 16;\n" :: "r"(s), "l"(gmem));
}
#define CP_COMMIT() asm volatile("cp.async.commit_group;\n" ::: "memory")
#define CP_WAIT0()  asm volatile("cp.async.wait_group 0;\n" ::: "memory")

// ---------------------------------------------------------------------------
// x: fp32 -> fp16
// ---------------------------------------------------------------------------
__global__ __launch_bounds__(256) void cvt_f16_kernel(
    const float* __restrict__ src, __half* __restrict__ dst, int n4)
{
    int i = blockIdx.x * blockDim.x + threadIdx.x;
    int stride = gridDim.x * blockDim.x;
    const float4* s4 = reinterpret_cast<const float4*>(src);
    uint2* d4 = reinterpret_cast<uint2*>(dst);
    for (; i < n4; i += stride) {
        float4 v = s4[i];
        __half2 h01 = __floats2half2_rn(v.x, v.y);
        __half2 h23 = __floats2half2_rn(v.z, v.w);
        uint2 p;
        p.x = *reinterpret_cast<unsigned*>(&h01);
        p.y = *reinterpret_cast<unsigned*>(&h23);
        d4[i] = p;
    }
}

// ---------------------------------------------------------------------------
// Weight transpose + cvt: W[k][n] fp32 -> WT[n][k] fp16. grid.z picks matrix.
// ---------------------------------------------------------------------------
__global__ __launch_bounds__(256) void wt_transpose_kernel(
    const float* __restrict__ W0, const float* __restrict__ W1,
    const float* __restrict__ W2, const float* __restrict__ W3,
    __half* __restrict__ out)
{
    __shared__ float tile[32][33];
    const float* W = (blockIdx.z == 0) ? W0 : (blockIdx.z == 1) ? W1 :
                     (blockIdx.z == 2) ? W2 : W3;
    __half* WT = out + (size_t)blockIdx.z * DD * DD;

    int n0 = blockIdx.x * 32;
    int k0 = blockIdx.y * 32;
    int tx = threadIdx.x, ty = threadIdx.y;
#pragma unroll
    for (int j = 0; j < 32; j += 8)
        tile[ty + j][tx] = W[(size_t)(k0 + ty + j) * DD + n0 + tx];
    __syncthreads();
#pragma unroll
    for (int j = 0; j < 32; j += 8)
        WT[(size_t)(n0 + ty + j) * DD + k0 + tx] = __float2half(tile[tx][ty + j]);
}

// ---------------------------------------------------------------------------
// FP16 tensor-core GEMM (unchanged structure from R11/R12)
// ---------------------------------------------------------------------------
#define HST 40
#define HTILE (128*HST)
#define GEMM_SMEM (2 * 2 * HTILE * 2)

__global__ __launch_bounds__(256) void h_gemm_kernel(
    const __half* __restrict__ A,
    const __half* __restrict__ B0, const __half* __restrict__ B1,
    const __half* __restrict__ B2,
    float* __restrict__ C0, float* __restrict__ C1, float* __restrict__ C2,
    __half* __restrict__ H0, __half* __restrict__ H1, __half* __restrict__ H2,
    int M, int N, int K)
{
    extern __shared__ __half hsm[];
    __half* sAb = hsm;
    __half* sBb = hsm + 2 * HTILE;

    const __half* Bt = (blockIdx.z == 0) ? B0 : (blockIdx.z == 1) ? B1 : B2;
    float*        C  = (blockIdx.z == 0) ? C0 : (blockIdx.z == 1) ? C1 : C2;
    __half*       Hp = (blockIdx.z == 0) ? H0 : (blockIdx.z == 1) ? H1 : H2;

    const int tid  = threadIdx.x;
    const int lane = tid & 31;
    const int wid  = tid >> 5;
    const int wm   = (wid & 3) * 32;
    const int wn   = (wid >> 2) * 64;
    const int g    = lane >> 2;
    const int t    = lane & 3;

    const int m0 = blockIdx.y * 128;
    const int n0 = blockIdx.x * 128;

    float acc[2][8][4];
#pragma unroll
    for (int mt = 0; mt < 2; mt++)
#pragma unroll
        for (int nt = 0; nt < 8; nt++)
#pragma unroll
            for (int i = 0; i < 4; i++) acc[mt][nt][i] = 0.f;

    auto load_stage = [&](int st, int k0) {
        __half* sA = sAb + st * HTILE;
        __half* sB = sBb + st * HTILE;
#pragma unroll
        for (int r = 0; r < 2; r++) {
            int f   = tid + r * 256;
            int row = f >> 2;
            int ch  = f & 3;
            cp_async16(&sA[row * HST + ch * 8],
                       &A[(size_t)(m0 + row) * K + k0 + ch * 8]);
        }
#pragma unroll
        for (int r = 0; r < 2; r++) {
            int f   = tid + r * 256;
            int row = f >> 2;
            int ch  = f & 3;
            cp_async16(&sB[row * HST + ch * 8],
                       &Bt[(size_t)(n0 + row) * K + k0 + ch * 8]);
        }
    };

    load_stage(0, 0);
    CP_COMMIT();
    CP_WAIT0();
    __syncthreads();

    int st = 0;
    for (int k0 = 0; k0 < K; k0 += 32) {
        const int nxt = k0 + 32;
        if (nxt < K) {
            load_stage(st ^ 1, nxt);
            CP_COMMIT();
        }

        const __half2* A2 = reinterpret_cast<const __half2*>(sAb + st * HTILE);
        const __half2* B2h = reinterpret_cast<const __half2*>(sBb + st * HTILE);
        const int H2ST = HST / 2;

#pragma unroll
        for (int ks = 0; ks < 2; ks++) {
            const int kb = ks * 8;
            unsigned af[2][4];
#pragma unroll
            for (int mt = 0; mt < 2; mt++) {
                const int row = wm + mt * 16;
                af[mt][0] = *reinterpret_cast<const unsigned*>(&A2[(row + g    ) * H2ST + kb + t    ]);
                af[mt][1] = *reinterpret_cast<const unsigned*>(&A2[(row + g + 8) * H2ST + kb + t    ]);
                af[mt][2] = *reinterpret_cast<const unsigned*>(&A2[(row + g    ) * H2ST + kb + t + 4]);
                af[mt][3] = *reinterpret_cast<const unsigned*>(&A2[(row + g + 8) * H2ST + kb + t + 4]);
            }
            unsigned bf[8][2];
#pragma unroll
            for (int nt = 0; nt < 8; nt++) {
                const int col = wn + nt * 8 + g;
                bf[nt][0] = *reinterpret_cast<const unsigned*>(&B2h[col * H2ST + kb + t    ]);
                bf[nt][1] = *reinterpret_cast<const unsigned*>(&B2h[col * H2ST + kb + t + 4]);
            }
#pragma unroll
            for (int mt = 0; mt < 2; mt++)
#pragma unroll
                for (int nt = 0; nt < 8; nt++)
                    mma_f16(acc[mt][nt], af[mt], bf[nt]);
        }

        if (nxt < K) CP_WAIT0();
        __syncthreads();
        st ^= 1;
    }

#pragma unroll
    for (int mt = 0; mt < 2; mt++) {
#pragma unroll
        for (int nt = 0; nt < 8; nt++) {
            const size_t row = (size_t)(m0 + wm + mt * 16 + g);
            const int    col = n0 + wn + nt * 8 + 2 * t;
            if (Hp) {
                __half2 lo = __floats2half2_rn(acc[mt][nt][0], acc[mt][nt][1]);
                __half2 hi = __floats2half2_rn(acc[mt][nt][2], acc[mt][nt][3]);
                *reinterpret_cast<__half2*>(&Hp[row * N + col])       = lo;
                *reinterpret_cast<__half2*>(&Hp[(row + 8) * N + col]) = hi;
            } else {
                float2 lo = make_float2(acc[mt][nt][0], acc[mt][nt][1]);
                float2 hi = make_float2(acc[mt][nt][2], acc[mt][nt][3]);
                *reinterpret_cast<float2*>(&C[row * N + col])       = lo;
                *reinterpret_cast<float2*>(&C[(row + 8) * N + col]) = hi;
            }
        }
    }
}

// ---------------------------------------------------------------------------
// Fused smolgen attention v13: block per (b, q-pair), 512 thr, 2 blk/SM.
// bk = q@a_k^T via MMA (prologue); av = P@a_v via MMA (epilogue, a_v stored
// transposed [d][k]); content+bq+PV scalar (diagonal terms). No softmax max.
// 2 barriers/head. All padded tiles stride 36 half2.
// ---------------------------------------------------------------------------
#define H2R 36                            // half2 per padded row

// float offsets
#define SQH_OFF   0                       // half2[2][16][36]   = 1152 floats
#define SKV_OFF   1152                    // half2[2buf][2][64][36] = 9216
#define SAK_OFF   (SKV_OFF + 9216)        // half2[2][64][36] = 4608 (a_k [k][d])
#define SAVT_OFF  (SAK_OFF + 4608)        // half2[2][64][36] = 4608 (a_v [d][k])
#define SBK_OFF   (SAVT_OFF + 4608)       // float[2][16][64] = 2048
#define SP_OFF    (SBK_OFF + 2048)        // float[2][16][72] = 2304
#define SLOG_OFF  (SP_OFF + 2304)         // float[2][64] = 128
#define SOUT1_OFF (SLOG_OFF + 128)        // float[2][16][64] = 2048
#define SRED_OFF  (SOUT1_OFF + 2048)      // float[1024]
#define ATTN_SMEM ((SRED_OFF + 1024) * 4) // 108544 bytes

__global__ __launch_bounds__(512, 2) void attn_kernel(
    const __half* __restrict__ Qh, const __half* __restrict__ Kt,
    const __half* __restrict__ V,
    const float* __restrict__ AQ, const float* __restrict__ AK,
    const float* __restrict__ AV, __half* __restrict__ Out)
{
    extern __shared__ float smem[];
    __half2* sQh2  = reinterpret_cast<__half2*>(smem + SQH_OFF);
    __half2* sKV2  = reinterpret_cast<__half2*>(smem + SKV_OFF);
    __half2* sAk2  = reinterpret_cast<__half2*>(smem + SAK_OFF);
    __half2* sAvT2 = reinterpret_cast<__half2*>(smem + SAVT_OFF);
    float*   sBk   = smem + SBK_OFF;
    float*   sP    = smem + SP_OFF;
    float*   sLog  = smem + SLOG_OFF;
    float*   sOut1 = smem + SOUT1_OFF;
    float*   sRed  = smem + SRED_OFF;

    const int t    = threadIdx.x;
    const int lane = t & 31;
    const int w    = t >> 5;               // warp 0..15
    const int b    = blockIdx.x >> 5;
    const int qg   = blockIdx.x & 31;
    const int row0 = b * TT + qg * 2;

    const int qp   = t >> 8;               // 0..1
    const int loc  = t & 255;
    const int lk   = loc >> 2;              // 0..63
    const int lp   = loc & 3;               // 0..3
    const int od2  = loc & 31;              // 0..31
    const int okp  = loc >> 5;              // 0..7 (warp-uniform)

    const int g  = lane >> 2;               // 0..7
    const int tt = lane & 3;                // 0..3

    // ---- prologue ----
    // q fp16 -> sQh2 (2 rows x 16 heads x 64 halves)
    if (t < 256) {
        int qq  = t >> 7;
        int rem = t & 127;
        int h   = rem >> 3;
        int j   = rem & 7;                  // 8-half chunk
        cp_async16(&sQh2[(qq * 16 + h) * H2R + 4 * j],
                   &Qh[(size_t)(row0 + qq) * DD + h * HDD + 8 * j]);
    }

    // a_k fp32 -> fp16 [k][d] padded; a_v fp32 -> fp16 TRANSPOSED [d][k]
#pragma unroll
    for (int r = 0; r < 4; r++) {
        int c   = t + r * 512;              // 0..2047 float4 chunks
        int qq  = c >> 10;
        int rm2 = c & 1023;
        int kk  = rm2 >> 4;
        int j   = rm2 & 15;                 // d base 4j
        const float* srck = AK + (((size_t)(row0 + qq)) * TT + kk) * HDD + 4 * j;
        const float* srcv = AV + (((size_t)(row0 + qq)) * TT + kk) * HDD + 4 * j;
        float4 vk = *reinterpret_cast<const float4*>(srck);
        float4 vv = *reinterpret_cast<const float4*>(srcv);
        // a_k: contiguous half2 pair write
        {
            __half2 h01 = __floats2half2_rn(vk.x, vk.y);
            __half2 h23 = __floats2half2_rn(vk.z, vk.w);
            uint2 packed;
            packed.x = *reinterpret_cast<unsigned*>(&h01);
            packed.y = *reinterpret_cast<unsigned*>(&h23);
            *reinterpret_cast<uint2*>(&sAk2[(qq * 64 + kk) * H2R + 2 * j]) = packed;
        }
        // a_v transposed: 4 scalar half stores to rows d = 4j..4j+3, col kk
        {
            __half* avh = reinterpret_cast<__half*>(sAvT2);
            float vs[4] = {vv.x, vv.y, vv.z, vv.w};
#pragma unroll
            for (int dlt = 0; dlt < 4; dlt++) {
                int d = 4 * j + dlt;
                avh[((qq * 64 + d) * H2R) * 2 + kk] = __float2half(vs[dlt]);
            }
        }
    }

    // a_q slice -> registers: float2 at d2 = lp + 4i
    float2 aq_r[8];
    {
        const float* aqp = AQ + (((size_t)(row0 + qp)) * TT + lk) * HDD + 2 * lp;
#pragma unroll
        for (int i = 0; i < 8; i++)
            aq_r[i] = *reinterpret_cast<const float2*>(aqp + 8 * i);
    }

    const __half* khB = Kt + (size_t)b * TT * DD;
    const __half* vhB = V  + (size_t)b * TT * DD;

    auto stage_kv = [&](int buf, int h) {
        const int hoff = h * HDD;
#pragma unroll
        for (int r = 0; r < 2; r++) {
            int c   = t + r * 512;
            int ten = c >> 9;
            int rem = c & 511;
            int kk  = rem >> 3;
            int j   = rem & 7;
            const __half* src = (ten ? vhB : khB) + (size_t)kk * DD + hoff + 8 * j;
            cp_async16(&sKV2[buf * 4608 + ten * 2304 + kk * H2R + 4 * j], src);
        }
    };

    stage_kv(0, 0);
    CP_COMMIT();
    CP_WAIT0();
    __syncthreads();

    // ---- bk MMA: bk[h,k] = sum_d q[h,d] * a_k[k,d] ----
    {
        const int qq = w >> 3;
        const int nt = w & 7;
        float acc[4] = {0.f, 0.f, 0.f, 0.f};
#pragma unroll
        for (int ks = 0; ks < 4; ks++) {
            unsigned a[4], b2[2];
            const __half2* qb = sQh2 + (qq * 16) * H2R;
            a[0] = *reinterpret_cast<const unsigned*>(&qb[(g    ) * H2R + ks * 8 + tt    ]);
            a[1] = *reinterpret_cast<const unsigned*>(&qb[(g + 8) * H2R + ks * 8 + tt    ]);
            a[2] = *reinterpret_cast<const unsigned*>(&qb[(g    ) * H2R + ks * 8 + tt + 4]);
            a[3] = *reinterpret_cast<const unsigned*>(&qb[(g + 8) * H2R + ks * 8 + tt + 4]);
            const __half2* kb2 = sAk2 + (qq * 64 + nt * 8 + g) * H2R;
            b2[0] = *reinterpret_cast<const unsigned*>(&kb2[ks * 8 + tt    ]);
            b2[1] = *reinterpret_cast<const unsigned*>(&kb2[ks * 8 + tt + 4]);
            mma_f16(acc, a, b2);
        }
        float* dst0 = &sBk[qp * 0 + qq * 1024 + g * 64 + nt * 8 + 2 * tt];
        dst0[0]  = acc[0];
        dst0[1]  = acc[1];
        float* dst1 = &sBk[qq * 1024 + (g + 8) * 64 + nt * 8 + 2 * tt];
        dst1[0]  = acc[2];
        dst1[1]  = acc[3];
    }
    __syncthreads();

    int cur = 0;
    for (int h = 0; h < HH; h++) {
        if (h + 1 < HH) {
            stage_kv(cur ^ 1, h + 1);
            CP_COMMIT();
        }

        // ---- logits: c2 = q.kv, bq2 = aq.kv; l = 0.125*c + bq + bk ----
        {
            const __half2* qh2 = sQh2 + (qp * 16 + h) * H2R;
            const __half2* kp  = sKV2 + cur * 4608 + lk * H2R + lp;
            float2 c2  = make_float2(0.f, 0.f);
            float2 bq2 = make_float2(0.f, 0.f);
#pragma unroll
            for (int i = 0; i < 8; i++) {
                float2 kv = __half22float2(kp[4 * i]);
                float2 qv = __half22float2(qh2[lp + 4 * i]);
                ffma2(c2,  qv,      kv);
                ffma2(bq2, aq_r[i], kv);
            }
            float l = (c2.x + c2.y) * 0.125f + (bq2.x + bq2.y);
            l += __shfl_xor_sync(0xffffffffu, l, 1);
            l += __shfl_xor_sync(0xffffffffu, l, 2);
            if (lp == 0)
                sLog[qp * 64 + lk] = l + sBk[qp * 1024 + h * 64 + lk];
        }
        __syncthreads();                    // barrier A

        // ---- per-warp softmax (no max subtraction; |l| small) ----
        float p0, p1;
        {
            float e0 = __expf(sLog[qp * 64 + lane]);
            float e1 = __expf(sLog[qp * 64 + lane + 32]);
            float s = e0 + e1;
#pragma unroll
            for (int o = 16; o; o >>= 1)
                s += __shfl_xor_sync(0xffffffffu, s, o);
            float inv = 1.0f / s;
            p0 = e0 * inv;
            p1 = e1 * inv;
        }
        // one warp per q writes P row for the av MMA
        if ((w & 7) == 0) {
            sP[(qp * 16 + h) * 72 + lane]      = p0;
            sP[(qp * 16 + h) * 72 + lane + 32] = p1;
        }

        // ---- PV partials (scalar; V only) ----
        {
            const __half2* vp = sKV2 + cur * 4608 + 2304 + okp * 8 * H2R + od2;
            float2 acc = make_float2(0.f, 0.f);
#pragma unroll
            for (int i = 0; i < 8; i++) {
                int k = okp * 8 + i;
                float pk = __shfl_sync(0xffffffffu, (okp < 4) ? p0 : p1, k & 31);
                float2 vv = __half22float2(vp[i * H2R]);
                acc.x = fmaf(pk, vv.x, acc.x);
                acc.y = fmaf(pk, vv.y, acc.y);
            }
            reinterpret_cast<float2*>(sRed)[(qp * 8 + okp) * 32 + od2] = acc;
        }
        CP_WAIT0();
        __syncthreads();                    // barrier B (sRed + staged KV + sP)

        // ---- accumulate PV into sOut1 ----
        if (t < 128) {
            int qq = t >> 6;
            int dd = t & 63;
            const float* rp = sRed + qq * 512 + dd;
            float o = rp[0] + rp[64] + rp[128] + rp[192]
                    + rp[256] + rp[320] + rp[384] + rp[448];
            sOut1[qq * 1024 + h * 64 + dd] = o;
        }
        cur ^= 1;
    }
    __syncthreads();                        // last sOut1 writes visible

    // ---- av MMA + epilogue: out[h,d] = sOut1[h,d] + P[h,:]@a_v[:,d] ----
    {
        const int qq = w >> 3;
        const int nt = w & 7;
        float acc[4] = {0.f, 0.f, 0.f, 0.f};
#pragma unroll
        for (int ks = 0; ks < 4; ks++) {
            unsigned a[4], b2[2];
            // A = P rows h = g, g+8; k-pairs kseq = 2tt(+1) + 16ks (and +8)
            const float* p0r = &sP[(qq * 16 + g    ) * 72 + ks * 16 + 2 * tt];
            const float* p1r = &sP[(qq * 16 + g + 8) * 72 + ks * 16 + 2 * tt];
            {
                float2 f0 = *reinterpret_cast<const float2*>(p0r);
                float2 f1 = *reinterpret_cast<const float2*>(p1r);
                float2 f2 = *reinterpret_cast<const float2*>(p0r + 8);
                float2 f3 = *reinterpret_cast<const float2*>(p1r + 8);
                __half2 h0 = __floats2half2_rn(f0.x, f0.y);
                __half2 h1 = __floats2half2_rn(f1.x, f1.y);
                __half2 h2 = __floats2half2_rn(f2.x, f2.y);
                __half2 h3 = __floats2half2_rn(f3.x, f3.y);
                a[0] = *reinterpret_cast<unsigned*>(&h0);
                a[1] = *reinterpret_cast<unsigned*>(&h1);
                a[2] = *reinterpret_cast<unsigned*>(&h2);
                a[3] = *reinterpret_cast<unsigned*>(&h3);
            }
            // B[k=kseq][n=d] from transposed a_v [d][k]
            const __half2* vb2 = sAvT2 + (qq * 64 + nt * 8 + g) * H2R;
            b2[0] = *reinterpret_cast<const unsigned*>(&vb2[ks * 8 + tt    ]);
            b2[1] = *reinterpret_cast<const unsigned*>(&vb2[ks * 8 + tt + 4]);
            mma_f16(acc, a, b2);
        }
        const int d0 = nt * 8 + 2 * tt;
        {
            const float* s0 = &sOut1[qq * 1024 + g * 64 + d0];
            __half2 o = __floats2half2_rn(acc[0] + s0[0], acc[1] + s0[1]);
            *reinterpret_cast<__half2*>(
                &Out[(size_t)(row0 + qq) * DD + g * HDD + d0]) = o;
        }
        {
            const float* s1 = &sOut1[qq * 1024 + (g + 8) * 64 + d0];
            __half2 o = __floats2half2_rn(acc[2] + s1[0], acc[3] + s1[1]);
            *reinterpret_cast<__half2*>(
                &Out[(size_t)(row0 + qq) * DD + (g + 8) * HDD + d0]) = o;
        }
    }
}

// ---------------------------------------------------------------------------
extern "C" void kernel_launch(void* const* d_in, const int* in_sizes, int n_in,
                              void* d_out, int out_size)
{
    const float* x  = (const float*)d_in[0];
    const float* aq = (const float*)d_in[1];
    const float* ak = (const float*)d_in[2];
    const float* av = (const float*)d_in[3];
    const float* Wq = (const float*)d_in[4];
    const float* Wk = (const float*)d_in[5];
    const float* Wv = (const float*)d_in[6];
    const float* Wo = (const float*)d_in[7];
    float* out = (float*)d_out;

    __half *pqh, *pkh, *pvh, *patth, *pxh, *pwth;
    cudaGetSymbolAddress((void**)&pqh,   g_qh);
    cudaGetSymbolAddress((void**)&pkh,   g_kh);
    cudaGetSymbolAddress((void**)&pvh,   g_vh);
    cudaGetSymbolAddress((void**)&patth, g_atth);
    cudaGetSymbolAddress((void**)&pxh,   g_xh);
    cudaGetSymbolAddress((void**)&pwth,  g_wth);

    const int W_ELEMS = DD * DD;

    cvt_f16_kernel<<<512, 256>>>(x, pxh, BT * DD / 4);
    {
        dim3 tgrid(DD / 32, DD / 32, 4);
        dim3 tblk(32, 8);
        wt_transpose_kernel<<<tgrid, tblk>>>(Wq, Wk, Wv, Wo, pwth);
    }

    cudaFuncSetAttribute((const void*)h_gemm_kernel,
                         cudaFuncAttributeMaxDynamicSharedMemorySize, GEMM_SMEM);

    // fused QKV projections: all fp16 outputs
    dim3 qkv_grid(DD / 128, BT / 128, 3);
    h_gemm_kernel<<<qkv_grid, 256, GEMM_SMEM>>>(
        pxh,
        pwth + 0 * W_ELEMS, pwth + 1 * W_ELEMS, pwth + 2 * W_ELEMS,
        nullptr, nullptr, nullptr,
        pqh, pkh, pvh,
        BT, DD, DD);

    cudaFuncSetAttribute((const void*)attn_kernel,
                         cudaFuncAttributeMaxDynamicSharedMemorySize, ATTN_SMEM);
    attn_kernel<<<BB * 32, 512, ATTN_SMEM>>>(pqh, pkh, pvh, aq, ak, av, patth);

    // Wo GEMM: att fp16 @ Wo^T -> out fp32
    dim3 o_grid(DD / 128, BT / 128, 1);
    h_gemm_kernel<<<o_grid, 256, GEMM_SMEM>>>(
        patth,
        pwth + 3 * W_ELEMS, pwth + 3 * W_ELEMS, pwth + 3 * W_ELEMS,
        out, out, out,
        nullptr, nullptr, nullptr,
        BT, DD, DD);
}

// round 17
// speedup vs baseline: 2.2709x; 1.1353x over previous
#include <cuda_runtime.h>
#include <cuda_fp16.h>
#include <stdint.h>
#include <math.h>

// Problem constants
#define BB 128
#define TT 64
#define DD 1024
#define HH 16
#define HDD 64
#define BT (BB*TT)        // 8192

// Scratch (device globals: allocation-free rule)
__device__ __half g_qh[BT*DD];
__device__ __half g_kh[BT*DD];
__device__ __half g_vh[BT*DD];
__device__ __half g_atth[BT*DD];
__device__ __half g_xh[BT*DD];        // fp16 x
__device__ __half g_wth[4*DD*DD];     // fp16 transposed Wq,Wk,Wv,Wo ([n][k])
__device__ float  g_cl[BT*HH*TT];     // content logits [row][h][k] (pre-scaled)
__device__ float  g_bq[BB*TT*TT*HH];  // bq bias [b][k][q][h]

__device__ __forceinline__ void mma_f16(float c[4], const unsigned a[4], const unsigned b[2]) {
    asm volatile(
        "mma.sync.aligned.m16n8k16.row.col.f32.f16.f16.f32 "
        "{%0,%1,%2,%3}, {%4,%5,%6,%7}, {%8,%9}, {%0,%1,%2,%3};"
        : "+f"(c[0]), "+f"(c[1]), "+f"(c[2]), "+f"(c[3])
        : "r"(a[0]), "r"(a[1]), "r"(a[2]), "r"(a[3]),
          "r"(b[0]), "r"(b[1]));
}

__device__ __forceinline__ void cp_async16(void* smem, const void* gmem) {
    unsigned s = (unsigned)__cvta_generic_to_shared(smem);
    asm volatile("cp.async.cg.shared.global [%0], [%1], 16;\n" :: "r"(s), "l"(gmem));
}
#define CP_COMMIT() asm volatile("cp.async.commit_group;\n" ::: "memory")
#define CP_WAIT0()  asm volatile("cp.async.wait_group 0;\n" ::: "memory")

// ---------------------------------------------------------------------------
// x: fp32 -> fp16
// ---------------------------------------------------------------------------
__global__ __launch_bounds__(256) void cvt_f16_kernel(
    const float* __restrict__ src, __half* __restrict__ dst, int n4)
{
    int i = blockIdx.x * blockDim.x + threadIdx.x;
    int stride = gridDim.x * blockDim.x;
    const float4* s4 = reinterpret_cast<const float4*>(src);
    uint2* d4 = reinterpret_cast<uint2*>(dst);
    for (; i < n4; i += stride) {
        float4 v = s4[i];
        __half2 h01 = __floats2half2_rn(v.x, v.y);
        __half2 h23 = __floats2half2_rn(v.z, v.w);
        uint2 p;
        p.x = *reinterpret_cast<unsigned*>(&h01);
        p.y = *reinterpret_cast<unsigned*>(&h23);
        d4[i] = p;
    }
}

// ---------------------------------------------------------------------------
// Weight transpose + cvt: W[k][n] fp32 -> WT[n][k] fp16.
// ---------------------------------------------------------------------------
__global__ __launch_bounds__(256) void wt_transpose_kernel(
    const float* __restrict__ W0, const float* __restrict__ W1,
    const float* __restrict__ W2, const float* __restrict__ W3,
    __half* __restrict__ out)
{
    __shared__ float tile[32][33];
    const float* W = (blockIdx.z == 0) ? W0 : (blockIdx.z == 1) ? W1 :
                     (blockIdx.z == 2) ? W2 : W3;
    __half* WT = out + (size_t)blockIdx.z * DD * DD;

    int n0 = blockIdx.x * 32;
    int k0 = blockIdx.y * 32;
    int tx = threadIdx.x, ty = threadIdx.y;
#pragma unroll
    for (int j = 0; j < 32; j += 8)
        tile[ty + j][tx] = W[(size_t)(k0 + ty + j) * DD + n0 + tx];
    __syncthreads();
#pragma unroll
    for (int j = 0; j < 32; j += 8)
        WT[(size_t)(n0 + ty + j) * DD + k0 + tx] = __float2half(tile[tx][ty + j]);
}

// ---------------------------------------------------------------------------
// FP16 tensor-core GEMM (m16n8k16, f32 accum), cp.async double buffer.
// ---------------------------------------------------------------------------
#define HST 40
#define HTILE (128*HST)
#define GEMM_SMEM (2 * 2 * HTILE * 2)

__global__ __launch_bounds__(256) void h_gemm_kernel(
    const __half* __restrict__ A,
    const __half* __restrict__ B0, const __half* __restrict__ B1,
    const __half* __restrict__ B2,
    float* __restrict__ C0, float* __restrict__ C1, float* __restrict__ C2,
    __half* __restrict__ H0, __half* __restrict__ H1, __half* __restrict__ H2,
    int M, int N, int K)
{
    extern __shared__ __half hsm[];
    __half* sAb = hsm;
    __half* sBb = hsm + 2 * HTILE;

    const __half* Bt = (blockIdx.z == 0) ? B0 : (blockIdx.z == 1) ? B1 : B2;
    float*        C  = (blockIdx.z == 0) ? C0 : (blockIdx.z == 1) ? C1 : C2;
    __half*       Hp = (blockIdx.z == 0) ? H0 : (blockIdx.z == 1) ? H1 : H2;

    const int tid  = threadIdx.x;
    const int lane = tid & 31;
    const int wid  = tid >> 5;
    const int wm   = (wid & 3) * 32;
    const int wn   = (wid >> 2) * 64;
    const int g    = lane >> 2;
    const int t    = lane & 3;

    const int m0 = blockIdx.y * 128;
    const int n0 = blockIdx.x * 128;

    float acc[2][8][4];
#pragma unroll
    for (int mt = 0; mt < 2; mt++)
#pragma unroll
        for (int nt = 0; nt < 8; nt++)
#pragma unroll
            for (int i = 0; i < 4; i++) acc[mt][nt][i] = 0.f;

    auto load_stage = [&](int st, int k0) {
        __half* sA = sAb + st * HTILE;
        __half* sB = sBb + st * HTILE;
#pragma unroll
        for (int r = 0; r < 2; r++) {
            int f   = tid + r * 256;
            int row = f >> 2;
            int ch  = f & 3;
            cp_async16(&sA[row * HST + ch * 8],
                       &A[(size_t)(m0 + row) * K + k0 + ch * 8]);
        }
#pragma unroll
        for (int r = 0; r < 2; r++) {
            int f   = tid + r * 256;
            int row = f >> 2;
            int ch  = f & 3;
            cp_async16(&sB[row * HST + ch * 8],
                       &Bt[(size_t)(n0 + row) * K + k0 + ch * 8]);
        }
    };

    load_stage(0, 0);
    CP_COMMIT();
    CP_WAIT0();
    __syncthreads();

    int st = 0;
    for (int k0 = 0; k0 < K; k0 += 32) {
        const int nxt = k0 + 32;
        if (nxt < K) {
            load_stage(st ^ 1, nxt);
            CP_COMMIT();
        }

        const __half2* A2 = reinterpret_cast<const __half2*>(sAb + st * HTILE);
        const __half2* B2h = reinterpret_cast<const __half2*>(sBb + st * HTILE);
        const int H2ST = HST / 2;

#pragma unroll
        for (int ks = 0; ks < 2; ks++) {
            const int kb = ks * 8;
            unsigned af[2][4];
#pragma unroll
            for (int mt = 0; mt < 2; mt++) {
                const int row = wm + mt * 16;
                af[mt][0] = *reinterpret_cast<const unsigned*>(&A2[(row + g    ) * H2ST + kb + t    ]);
                af[mt][1] = *reinterpret_cast<const unsigned*>(&A2[(row + g + 8) * H2ST + kb + t    ]);
                af[mt][2] = *reinterpret_cast<const unsigned*>(&A2[(row + g    ) * H2ST + kb + t + 4]);
                af[mt][3] = *reinterpret_cast<const unsigned*>(&A2[(row + g + 8) * H2ST + kb + t + 4]);
            }
            unsigned bf[8][2];
#pragma unroll
            for (int nt = 0; nt < 8; nt++) {
                const int col = wn + nt * 8 + g;
                bf[nt][0] = *reinterpret_cast<const unsigned*>(&B2h[col * H2ST + kb + t    ]);
                bf[nt][1] = *reinterpret_cast<const unsigned*>(&B2h[col * H2ST + kb + t + 4]);
            }
#pragma unroll
            for (int mt = 0; mt < 2; mt++)
#pragma unroll
                for (int nt = 0; nt < 8; nt++)
                    mma_f16(acc[mt][nt], af[mt], bf[nt]);
        }

        if (nxt < K) CP_WAIT0();
        __syncthreads();
        st ^= 1;
    }

#pragma unroll
    for (int mt = 0; mt < 2; mt++) {
#pragma unroll
        for (int nt = 0; nt < 8; nt++) {
            const size_t row = (size_t)(m0 + wm + mt * 16 + g);
            const int    col = n0 + wn + nt * 8 + 2 * t;
            if (Hp) {
                __half2 lo = __floats2half2_rn(acc[mt][nt][0], acc[mt][nt][1]);
                __half2 hi = __floats2half2_rn(acc[mt][nt][2], acc[mt][nt][3]);
                *reinterpret_cast<__half2*>(&Hp[row * N + col])       = lo;
                *reinterpret_cast<__half2*>(&Hp[(row + 8) * N + col]) = hi;
            } else {
                float2 lo = make_float2(acc[mt][nt][0], acc[mt][nt][1]);
                float2 hi = make_float2(acc[mt][nt][2], acc[mt][nt][3]);
                *reinterpret_cast<float2*>(&C[row * N + col])       = lo;
                *reinterpret_cast<float2*>(&C[(row + 8) * N + col]) = hi;
            }
        }
    }
}

// ---------------------------------------------------------------------------
// content kernel: per (b,h) block, Cl[q,k] = 0.125 * Q_h(64x64) @ K_h^T(64x64)
// ---------------------------------------------------------------------------
__global__ __launch_bounds__(128) void content_kernel(
    const __half* __restrict__ Qh, const __half* __restrict__ Kh,
    float* __restrict__ Cl)
{
    __shared__ __half2 sQK[2 * 64 * 36];   // Q tile then K tile, stride 36 h2

    const int b = blockIdx.x >> 4;
    const int h = blockIdx.x & 15;
    const int tid  = threadIdx.x;
    const int lane = tid & 31;
    const int w    = tid >> 5;
    const int g    = lane >> 2;
    const int tt   = lane & 3;

    // stage Q and K tiles (1024 16B chunks total)   [FIX: r < 8, was r < 4]
#pragma unroll
    for (int r = 0; r < 8; r++) {
        int c   = tid + r * 128;
        int isK = c >> 9;
        int cc  = c & 511;
        int row = cc >> 3;
        int j   = cc & 7;
        const __half* src = (isK ? Kh : Qh) +
            (size_t)(b * 64 + row) * DD + h * HDD + 8 * j;
        cp_async16(&sQK[isK * 2304 + row * 36 + 4 * j], src);
    }
    CP_COMMIT();
    CP_WAIT0();
    __syncthreads();

    const __half2* sQ = sQK;
    const __half2* sK = sQK + 2304;

    float acc[8][4];
#pragma unroll
    for (int nt = 0; nt < 8; nt++)
#pragma unroll
        for (int i = 0; i < 4; i++) acc[nt][i] = 0.f;

#pragma unroll
    for (int ks = 0; ks < 4; ks++) {
        unsigned a[4];
        const __half2* qb = sQ + (w * 16) * 36;
        a[0] = *reinterpret_cast<const unsigned*>(&qb[(g    ) * 36 + ks * 8 + tt    ]);
        a[1] = *reinterpret_cast<const unsigned*>(&qb[(g + 8) * 36 + ks * 8 + tt    ]);
        a[2] = *reinterpret_cast<const unsigned*>(&qb[(g    ) * 36 + ks * 8 + tt + 4]);
        a[3] = *reinterpret_cast<const unsigned*>(&qb[(g + 8) * 36 + ks * 8 + tt + 4]);
        unsigned bf[8][2];
#pragma unroll
        for (int nt = 0; nt < 8; nt++) {
            const __half2* kb = sK + (nt * 8 + g) * 36;
            bf[nt][0] = *reinterpret_cast<const unsigned*>(&kb[ks * 8 + tt    ]);
            bf[nt][1] = *reinterpret_cast<const unsigned*>(&kb[ks * 8 + tt + 4]);
        }
#pragma unroll
        for (int nt = 0; nt < 8; nt++)
            mma_f16(acc[nt], a, bf[nt]);
    }

    const float S = 0.125f;
#pragma unroll
    for (int nt = 0; nt < 8; nt++) {
        int q0 = b * 64 + w * 16 + g;
        int kx = nt * 8 + 2 * tt;
        *reinterpret_cast<float2*>(&Cl[((size_t)q0 * 16 + h) * 64 + kx]) =
            make_float2(acc[nt][0] * S, acc[nt][1] * S);
        *reinterpret_cast<float2*>(&Cl[((size_t)(q0 + 8) * 16 + h) * 64 + kx]) =
            make_float2(acc[nt][2] * S, acc[nt][3] * S);
    }
}

// ---------------------------------------------------------------------------
// bq kernel: per (b,k) block, Bq[q,h] = AQ[b,q,k,:](64x64) @ K[b,k,:,:]^T(64x16)
// ---------------------------------------------------------------------------
__global__ __launch_bounds__(128) void bq_kernel(
    const float* __restrict__ AQ, const __half* __restrict__ Kh,
    float* __restrict__ Bq)
{
    __shared__ float   sA[64 * 68];      // [q][d] fp32, stride 68
    __shared__ __half2 sK[16 * 36];      // [h][d] fp16

    const int b = blockIdx.x >> 6;
    const int k = blockIdx.x & 63;
    const int tid  = threadIdx.x;
    const int lane = tid & 31;
    const int w    = tid >> 5;
    const int g    = lane >> 2;
    const int tt   = lane & 3;

#pragma unroll
    for (int r = 0; r < 8; r++) {
        int c   = tid + r * 128;
        int row = c >> 4;
        int j   = c & 15;
        cp_async16(&sA[row * 68 + 4 * j],
                   AQ + ((size_t)((b * 64 + row) * 64 + k)) * 64 + 4 * j);
    }
    {
        int h = tid >> 3;
        int j = tid & 7;
        cp_async16(&sK[h * 36 + 4 * j],
                   Kh + (size_t)(b * 64 + k) * DD + h * HDD + 8 * j);
    }
    CP_COMMIT();
    CP_WAIT0();
    __syncthreads();

    float acc[2][4];
#pragma unroll
    for (int nt = 0; nt < 2; nt++)
#pragma unroll
        for (int i = 0; i < 4; i++) acc[nt][i] = 0.f;

#pragma unroll
    for (int ks = 0; ks < 4; ks++) {
        unsigned a[4];
        {
            float2 f0 = *reinterpret_cast<const float2*>(&sA[(w * 16 + g    ) * 68 + ks * 16 + 2 * tt]);
            float2 f1 = *reinterpret_cast<const float2*>(&sA[(w * 16 + g + 8) * 68 + ks * 16 + 2 * tt]);
            float2 f2 = *reinterpret_cast<const float2*>(&sA[(w * 16 + g    ) * 68 + ks * 16 + 2 * tt + 8]);
            float2 f3 = *reinterpret_cast<const float2*>(&sA[(w * 16 + g + 8) * 68 + ks * 16 + 2 * tt + 8]);
            __half2 h0 = __floats2half2_rn(f0.x, f0.y);
            __half2 h1 = __floats2half2_rn(f1.x, f1.y);
            __half2 h2 = __floats2half2_rn(f2.x, f2.y);
            __half2 h3 = __floats2half2_rn(f3.x, f3.y);
            a[0] = *reinterpret_cast<unsigned*>(&h0);
            a[1] = *reinterpret_cast<unsigned*>(&h1);
            a[2] = *reinterpret_cast<unsigned*>(&h2);
            a[3] = *reinterpret_cast<unsigned*>(&h3);
        }
#pragma unroll
        for (int nt = 0; nt < 2; nt++) {
            unsigned bf[2];
            const __half2* kb = sK + (nt * 8 + g) * 36;
            bf[0] = *reinterpret_cast<const unsigned*>(&kb[ks * 8 + tt    ]);
            bf[1] = *reinterpret_cast<const unsigned*>(&kb[ks * 8 + tt + 4]);
            mma_f16(acc[nt], a, bf);
        }
    }

#pragma unroll
    for (int nt = 0; nt < 2; nt++) {
        int q0 = w * 16 + g;
        int hx = nt * 8 + 2 * tt;
        size_t base = ((size_t)(b * 64 + k) * 64);
        *reinterpret_cast<float2*>(&Bq[(base + q0) * 16 + hx]) =
            make_float2(acc[nt][0], acc[nt][1]);
        *reinterpret_cast<float2*>(&Bq[(base + q0 + 8) * 16 + hx]) =
            make_float2(acc[nt][2], acc[nt][3]);
    }
}

// ---------------------------------------------------------------------------
// Fused smolgen attention v16: block per (b, q-pair), 512 thr, 2 blk/SM.
// Logits precomputed: sL = cl (cp.async) + bq (LDG add) + bk (in-block MMA).
// Head loop: softmax + PV (warp k-split, shfl reduce) + V prefetch.
// ONE barrier per head. av via MMA at end.
// ---------------------------------------------------------------------------
#define H2R 36

#define SQH_OFF   0                      // h2 [2][16][36]     = 1152
#define SV_OFF    1152                   // h2 [2buf][64][36]  = 4608
#define SAK_OFF   (SV_OFF + 4608)        // h2 [2q][64][36]    = 4608
#define SAVT_OFF  (SAK_OFF + 4608)       // h2 [2q][64][36]    = 4608
#define SL_OFF    (SAVT_OFF + 4608)      // f32 [2][16][64]    = 2048
#define SP_OFF    (SL_OFF + 2048)        // f32 [2][16][72]    = 2304
#define SOUT1_OFF (SP_OFF + 2304)        // f32 [2][16][64]    = 2048
#define ATTN_SMEM ((SOUT1_OFF + 2048) * 4)   // 85504 B

__global__ __launch_bounds__(512, 2) void attn_kernel(
    const __half* __restrict__ Qh, const __half* __restrict__ V,
    const float* __restrict__ Cl, const float* __restrict__ Bq,
    const float* __restrict__ AK, const float* __restrict__ AV,
    __half* __restrict__ Out)
{
    extern __shared__ float smem[];
    __half2* sQh2  = reinterpret_cast<__half2*>(smem + SQH_OFF);
    __half2* sV2   = reinterpret_cast<__half2*>(smem + SV_OFF);
    __half2* sAk2  = reinterpret_cast<__half2*>(smem + SAK_OFF);
    __half2* sAvT2 = reinterpret_cast<__half2*>(smem + SAVT_OFF);
    float*   sL    = smem + SL_OFF;
    float*   sP    = smem + SP_OFF;
    float*   sOut1 = smem + SOUT1_OFF;

    const int t    = threadIdx.x;
    const int lane = t & 31;
    const int w    = t >> 5;
    const int b    = blockIdx.x >> 5;
    const int qg   = blockIdx.x & 31;
    const int row0 = b * TT + qg * 2;

    const int qp   = t >> 8;             // 0..1
    const int loc  = t & 255;
    const int g    = lane >> 2;
    const int tt   = lane & 3;

    const __half* vhB = V + (size_t)b * TT * DD;

    // ---------------- prologue ----------------
    if (t < 256) {
        int qq  = t >> 7;
        int rem = t & 127;
        int h   = rem >> 3;
        int j   = rem & 7;
        cp_async16(&sQh2[(qq * 16 + h) * H2R + 4 * j],
                   &Qh[(size_t)(row0 + qq) * DD + h * HDD + 8 * j]);
    }
    {
        int qq  = t >> 8;
        int rem = t & 255;
        int h   = rem >> 4;
        int j   = rem & 15;
        cp_async16(&sL[qq * 1024 + h * 64 + 4 * j],
                   &Cl[((size_t)(row0 + qq) * 16 + h) * 64 + 4 * j]);
    }
    {
        int kk = t >> 3;
        int j  = t & 7;
        cp_async16(&sV2[kk * H2R + 4 * j],
                   vhB + (size_t)kk * DD + 0 * HDD + 8 * j);
    }
    CP_COMMIT();

    // a_k / a_v staging; a_v transposed
#pragma unroll
    for (int r = 0; r < 4; r++) {
        int c   = t + r * 512;
        int qq  = c >> 10;
        int rm2 = c & 1023;
        int kk  = rm2 >> 4;
        int j   = rm2 & 15;
        const float* srck = AK + (((size_t)(row0 + qq)) * TT + kk) * HDD + 4 * j;
        const float* srcv = AV + (((size_t)(row0 + qq)) * TT + kk) * HDD + 4 * j;
        float4 vk = *reinterpret_cast<const float4*>(srck);
        float4 vv = *reinterpret_cast<const float4*>(srcv);
        {
            __half2 h01 = __floats2half2_rn(vk.x, vk.y);
            __half2 h23 = __floats2half2_rn(vk.z, vk.w);
            uint2 packed;
            packed.x = *reinterpret_cast<unsigned*>(&h01);
            packed.y = *reinterpret_cast<unsigned*>(&h23);
            *reinterpret_cast<uint2*>(&sAk2[(qq * 64 + kk) * H2R + 2 * j]) = packed;
        }
        {
            __half* avh = reinterpret_cast<__half*>(sAvT2);
            float vs[4] = {vv.x, vv.y, vv.z, vv.w};
#pragma unroll
            for (int dlt = 0; dlt < 4; dlt++) {
                int d = 4 * j + dlt;
                avh[((qq * 64 + d) * H2R) * 2 + kk] = __float2half(vs[dlt]);
            }
        }
    }

    float4 bqv;
    int bq_qq, bq_k, bq_hc;
    {
        bq_qq = t >> 8;
        int rem = t & 255;
        bq_k  = rem >> 2;
        bq_hc = rem & 3;
        bqv = *reinterpret_cast<const float4*>(
            &Bq[((size_t)(b * 64 + bq_k) * 64 + (qg * 2 + bq_qq)) * 16 + 4 * bq_hc]);
    }

    CP_WAIT0();
    __syncthreads();

    // add bq into sL
    {
        float* base = &sL[bq_qq * 1024 + (4 * bq_hc) * 64 + bq_k];
        base[0]   += bqv.x;
        base[64]  += bqv.y;
        base[128] += bqv.z;
        base[192] += bqv.w;
    }
    __syncthreads();

    // bk MMA: bk[h,k] accumulated into sL
    {
        const int qq = w >> 3;
        const int nt = w & 7;
        float acc[4] = {0.f, 0.f, 0.f, 0.f};
#pragma unroll
        for (int ks = 0; ks < 4; ks++) {
            unsigned a[4], b2[2];
            const __half2* qb = sQh2 + (qq * 16) * H2R;
            a[0] = *reinterpret_cast<const unsigned*>(&qb[(g    ) * H2R + ks * 8 + tt    ]);
            a[1] = *reinterpret_cast<const unsigned*>(&qb[(g + 8) * H2R + ks * 8 + tt    ]);
            a[2] = *reinterpret_cast<const unsigned*>(&qb[(g    ) * H2R + ks * 8 + tt + 4]);
            a[3] = *reinterpret_cast<const unsigned*>(&qb[(g + 8) * H2R + ks * 8 + tt + 4]);
            const __half2* kb2 = sAk2 + (qq * 64 + nt * 8 + g) * H2R;
            b2[0] = *reinterpret_cast<const unsigned*>(&kb2[ks * 8 + tt    ]);
            b2[1] = *reinterpret_cast<const unsigned*>(&kb2[ks * 8 + tt + 4]);
            mma_f16(acc, a, b2);
        }
        float* d0 = &sL[qq * 1024 + g * 64 + nt * 8 + 2 * tt];
        d0[0] += acc[0];
        d0[1] += acc[1];
        float* d1 = &sL[qq * 1024 + (g + 8) * 64 + nt * 8 + 2 * tt];
        d1[0] += acc[2];
        d1[1] += acc[3];
    }
    __syncthreads();

    // ---------------- head loop: 1 barrier per head ----------------
    const int d2 = loc >> 3;             // 0..31 (half2 d index)
    const int ks = loc & 7;              // k-split within warp

    int cur = 0;
    for (int h = 0; h < HH; h++) {
        if (h + 1 < HH) {
            const int hoff = (h + 1) * HDD;
            int kk = t >> 3;
            int j  = t & 7;
            cp_async16(&sV2[(cur ^ 1) * 2304 + kk * H2R + 4 * j],
                       vhB + (size_t)kk * DD + hoff + 8 * j);
            CP_COMMIT();
        }

        float p0, p1;
        {
            float e0 = __expf(sL[qp * 1024 + h * 64 + lane]);
            float e1 = __expf(sL[qp * 1024 + h * 64 + lane + 32]);
            float s = e0 + e1;
#pragma unroll
            for (int o = 16; o; o >>= 1)
                s += __shfl_xor_sync(0xffffffffu, s, o);
            float inv = 1.0f / s;
            p0 = e0 * inv;
            p1 = e1 * inv;
        }
        if ((w & 7) == 0) {
            sP[(qp * 16 + h) * 72 + lane]      = p0;
            sP[(qp * 16 + h) * 72 + lane + 32] = p1;
        }

        // PV partials: k = ks + 8i
        {
            const __half2* vp = sV2 + cur * 2304 + d2;
            float2 acc = make_float2(0.f, 0.f);
#pragma unroll
            for (int i = 0; i < 8; i++) {
                int k = ks + 8 * i;
                float pk = __shfl_sync(0xffffffffu, (i < 4) ? p0 : p1, k & 31);
                float2 vv = __half22float2(vp[k * H2R]);
                acc.x = fmaf(pk, vv.x, acc.x);
                acc.y = fmaf(pk, vv.y, acc.y);
            }
            acc.x += __shfl_xor_sync(0xffffffffu, acc.x, 1);
            acc.y += __shfl_xor_sync(0xffffffffu, acc.y, 1);
            acc.x += __shfl_xor_sync(0xffffffffu, acc.x, 2);
            acc.y += __shfl_xor_sync(0xffffffffu, acc.y, 2);
            acc.x += __shfl_xor_sync(0xffffffffu, acc.x, 4);
            acc.y += __shfl_xor_sync(0xffffffffu, acc.y, 4);
            if (ks == 0)
                *reinterpret_cast<float2*>(&sOut1[qp * 1024 + h * 64 + 2 * d2]) = acc;
        }

        CP_WAIT0();
        __syncthreads();
        cur ^= 1;
    }

    // ---------------- av MMA + epilogue ----------------
    {
        const int qq = w >> 3;
        const int nt = w & 7;
        float acc[4] = {0.f, 0.f, 0.f, 0.f};
#pragma unroll
        for (int kstep = 0; kstep < 4; kstep++) {
            unsigned a[4], b2[2];
            const float* p0r = &sP[(qq * 16 + g    ) * 72 + kstep * 16 + 2 * tt];
            const float* p1r = &sP[(qq * 16 + g + 8) * 72 + kstep * 16 + 2 * tt];
            {
                float2 f0 = *reinterpret_cast<const float2*>(p0r);
                float2 f1 = *reinterpret_cast<const float2*>(p1r);
                float2 f2 = *reinterpret_cast<const float2*>(p0r + 8);
                float2 f3 = *reinterpret_cast<const float2*>(p1r + 8);
                __half2 h0 = __floats2half2_rn(f0.x, f0.y);
                __half2 h1 = __floats2half2_rn(f1.x, f1.y);
                __half2 h2 = __floats2half2_rn(f2.x, f2.y);
                __half2 h3 = __floats2half2_rn(f3.x, f3.y);
                a[0] = *reinterpret_cast<unsigned*>(&h0);
                a[1] = *reinterpret_cast<unsigned*>(&h1);
                a[2] = *reinterpret_cast<unsigned*>(&h2);
                a[3] = *reinterpret_cast<unsigned*>(&h3);
            }
            const __half2* vb2 = sAvT2 + (qq * 64 + nt * 8 + g) * H2R;
            b2[0] = *reinterpret_cast<const unsigned*>(&vb2[kstep * 8 + tt    ]);
            b2[1] = *reinterpret_cast<const unsigned*>(&vb2[kstep * 8 + tt + 4]);
            mma_f16(acc, a, b2);
        }
        const int d0 = nt * 8 + 2 * tt;
        {
            const float* s0 = &sOut1[qq * 1024 + g * 64 + d0];
            __half2 o = __floats2half2_rn(acc[0] + s0[0], acc[1] + s0[1]);
            *reinterpret_cast<__half2*>(
                &Out[(size_t)(row0 + qq) * DD + g * HDD + d0]) = o;
        }
        {
            const float* s1 = &sOut1[qq * 1024 + (g + 8) * 64 + d0];
            __half2 o = __floats2half2_rn(acc[2] + s1[0], acc[3] + s1[1]);
            *reinterpret_cast<__half2*>(
                &Out[(size_t)(row0 + qq) * DD + (g + 8) * HDD + d0]) = o;
        }
    }
}

// ---------------------------------------------------------------------------
extern "C" void kernel_launch(void* const* d_in, const int* in_sizes, int n_in,
                              void* d_out, int out_size)
{
    const float* x  = (const float*)d_in[0];
    const float* aq = (const float*)d_in[1];
    const float* ak = (const float*)d_in[2];
    const float* av = (const float*)d_in[3];
    const float* Wq = (const float*)d_in[4];
    const float* Wk = (const float*)d_in[5];
    const float* Wv = (const float*)d_in[6];
    const float* Wo = (const float*)d_in[7];
    float* out = (float*)d_out;

    __half *pqh, *pkh, *pvh, *patth, *pxh, *pwth;
    float *pcl, *pbq;
    cudaGetSymbolAddress((void**)&pqh,   g_qh);
    cudaGetSymbolAddress((void**)&pkh,   g_kh);
    cudaGetSymbolAddress((void**)&pvh,   g_vh);
    cudaGetSymbolAddress((void**)&patth, g_atth);
    cudaGetSymbolAddress((void**)&pxh,   g_xh);
    cudaGetSymbolAddress((void**)&pwth,  g_wth);
    cudaGetSymbolAddress((void**)&pcl,   g_cl);
    cudaGetSymbolAddress((void**)&pbq,   g_bq);

    const int W_ELEMS = DD * DD;

    cvt_f16_kernel<<<512, 256>>>(x, pxh, BT * DD / 4);
    {
        dim3 tgrid(DD / 32, DD / 32, 4);
        dim3 tblk(32, 8);
        wt_transpose_kernel<<<tgrid, tblk>>>(Wq, Wk, Wv, Wo, pwth);
    }

    cudaFuncSetAttribute((const void*)h_gemm_kernel,
                         cudaFuncAttributeMaxDynamicSharedMemorySize, GEMM_SMEM);

    dim3 qkv_grid(DD / 128, BT / 128, 3);
    h_gemm_kernel<<<qkv_grid, 256, GEMM_SMEM>>>(
        pxh,
        pwth + 0 * W_ELEMS, pwth + 1 * W_ELEMS, pwth + 2 * W_ELEMS,
        nullptr, nullptr, nullptr,
        pqh, pkh, pvh,
        BT, DD, DD);

    content_kernel<<<BB * HH, 128>>>(pqh, pkh, pcl);
    bq_kernel<<<BB * TT, 128>>>(aq, pkh, pbq);

    cudaFuncSetAttribute((const void*)attn_kernel,
                         cudaFuncAttributeMaxDynamicSharedMemorySize, ATTN_SMEM);
    attn_kernel<<<BB * 32, 512, ATTN_SMEM>>>(pqh, pvh, pcl, pbq, ak, av, patth);

    dim3 o_grid(DD / 128, BT / 128, 1);
    h_gemm_kernel<<<o_grid, 256, GEMM_SMEM>>>(
        patth,
        pwth + 3 * W_ELEMS, pwth + 3 * W_ELEMS, pwth + 3 * W_ELEMS,
        out, out, out,
        nullptr, nullptr, nullptr,
        BT, DD, DD);
}